// round 7
// baseline (speedup 1.0000x reference)
#include <cuda_runtime.h>
#include <math.h>

// ---------------------------------------------------------------------------
// AECFModel fused multimodal classifier — fp32, row-pair f32x2 FMA on
// transposed smem tiles, pre-sorted branches, 2 CTAs/SM x 256 thr x 32 rows.
// H=256, ID=TD=512, NC=80, B=131072.
// ---------------------------------------------------------------------------

typedef unsigned long long u64;

__device__ __forceinline__ u64 pk2(float x, float y) {
    u64 r; asm("mov.b64 %0,{%1,%2};" : "=l"(r) : "f"(x), "f"(y)); return r;
}
__device__ __forceinline__ void fma2(u64& d, u64 a, u64 b) {
    asm("fma.rn.f32x2 %0,%1,%2,%0;" : "+l"(d) : "l"(a), "l"(b));
}
__device__ __forceinline__ u64 mul2(u64 a, u64 b) {
    u64 r; asm("mul.rn.f32x2 %0,%1,%2;" : "=l"(r) : "l"(a), "l"(b)); return r;
}
__device__ __forceinline__ float2 up2(u64 d) {
    float2 r; asm("mov.b64 {%0,%1},%2;" : "=f"(r.x), "=f"(r.y) : "l"(d)); return r;
}

// Per-launch precomputed tensors (device-global scratch; rewritten every call).
__device__ float g_q[256];
__device__ float g_wk[4 * 256];
__device__ float g_ck[4];
__device__ float g_tmp[256];
__device__ float g_Wof[256 * 512];  // Wo @ W_fp
__device__ float g_bof[512];        // (bv@Wo+bo) @ W_fp + b_fp

// ---------------------------- combined setup -------------------------------
// grid 17 x 256. Block 0: small precomputes. Blocks 1..16: Wof tiles.
__global__ void setup_all(const float* __restrict__ fq, const float* __restrict__ Wq,
                          const float* __restrict__ bq, const float* __restrict__ Wk,
                          const float* __restrict__ bk, const float* __restrict__ bv,
                          const float* __restrict__ Wo, const float* __restrict__ bo,
                          const float* __restrict__ Wfp, const float* __restrict__ bfp) {
    __shared__ float sA[64 * 65];
    int t = threadIdx.x;
    if (blockIdx.x == 0) {
        {   // g_q
            float s = bq[t];
#pragma unroll 8
            for (int k = 0; k < 256; k++) s = fmaf(fq[k], Wq[k * 256 + t], s);
            g_q[t] = s;
        }
        __syncthreads();
#pragma unroll
        for (int l = 0; l < 4; l++) {   // g_wk
            int idx = t + l * 256;
            int h = idx >> 8, j = idx & 255;
            float s = 0.f;
#pragma unroll 8
            for (int d = 0; d < 64; d++)
                s = fmaf(Wk[j * 256 + h * 64 + d], g_q[h * 64 + d], s);
            g_wk[h * 256 + j] = s;
        }
        if (t < 4) {                    // g_ck
            float c = 0.f;
#pragma unroll 8
            for (int d = 0; d < 64; d++) c = fmaf(bk[t * 64 + d], g_q[t * 64 + d], c);
            g_ck[t] = c;
        }
        __syncthreads();
        {   // g_tmp = bv@Wo + bo
            float s = bo[t];
#pragma unroll 8
            for (int k = 0; k < 256; k++) s = fmaf(bv[k], Wo[k * 256 + t], s);
            g_tmp[t] = s;
        }
        __syncthreads();
#pragma unroll
        for (int l = 0; l < 2; l++) {   // g_bof
            int j = t + l * 256;
            float s = bfp[j];
#pragma unroll 8
            for (int m = 0; m < 256; m++) s = fmaf(g_tmp[m], Wfp[m * 512 + j], s);
            g_bof[j] = s;
        }
        return;
    }
    // ---- Wof tile ----
    int bid = blockIdx.x - 1;
    int tx = t & 31, ty = t >> 5;
    int it = bid >> 2, jt = bid & 3;
    float acc[8][4];
#pragma unroll
    for (int i = 0; i < 8; i++)
#pragma unroll
        for (int c = 0; c < 4; c++) acc[i][c] = 0.f;

    for (int mc = 0; mc < 256; mc += 64) {
        __syncthreads();
#pragma unroll
        for (int l = 0; l < 16; l++) {
            int idx = t + l * 256;
            int r = idx >> 6, k = idx & 63;
            sA[r * 65 + k] = Wo[(it * 64 + r) * 256 + mc + k];
        }
        __syncthreads();
#pragma unroll 2
        for (int k = 0; k < 64; k++) {
            const float* Wp = Wfp + (size_t)(mc + k) * 512 + jt * 128 + tx;
            float w[4];
#pragma unroll
            for (int c = 0; c < 4; c++) w[c] = Wp[c * 32];
#pragma unroll
            for (int i = 0; i < 8; i++) {
                float a = sA[(ty * 8 + i) * 65 + k];
#pragma unroll
                for (int c = 0; c < 4; c++) acc[i][c] = fmaf(a, w[c], acc[i][c]);
            }
        }
    }
    __syncthreads();
#pragma unroll
    for (int i = 0; i < 8; i++)
#pragma unroll
        for (int c = 0; c < 4; c++)
            g_Wof[(size_t)(it * 64 + ty * 8 + i) * 512 + jt * 128 + tx + 32 * c] =
                acc[i][c];
}

// ------------------------------- main kernel -------------------------------
// 32 rows/CTA (sorted slots), 256 threads (8 warps), 2 CTAs/SM.
// warp w: rg = w&3 (slots rg*8..+7 as 4 row-pairs), nh = w>>2 (N half).
// All smem tensors transposed [k][slot], stride 34 (even -> LDS.64 pairs).
//
// smem (float offsets):
//   e0T @ 0     [256][34]   e1T @ 8704 [256][34]   pT @ 17408 [256][34]
//   sAT @ 26112 [64][34] staging (also norm partials pre-pass)
//   attn @ 28288 [32][4]   flag @ 28416  perm @ 28448  sbr @ 28480
//   overlays: fusedT @ 0 [512][34] (= e0T+e1T exactly), h1T @ 17408 [256][34]

#define S34 34
#define OFF_E1   8704
#define OFF_PT   17408
#define OFF_SAT  26112
#define OFF_ATTN 28288
#define OFF_FLAG 28416
#define OFF_PERM 28448
#define OFF_SBR  28480
#define SMEM_FLOATS 28512
#define SMEM_BYTES (SMEM_FLOATS * 4)

// P5 segment: K=256 -> this thread's 8 cols (nh*256 + tx*8). Row-pair A from AT.
template <bool MASKED>
__device__ __forceinline__ void gemm_seg(u64 (&facc)[4][8],
                                         const float* __restrict__ AT,
                                         const float* __restrict__ W,
                                         const u64* mp, int rg, int nh, int tx) {
    const float* Wb = W + nh * 256 + tx * 8;
    const float* Ab = AT + rg * 8;
#pragma unroll 2
    for (int k = 0; k < 256; k++) {
        float4 wa = *(const float4*)(Wb + (size_t)k * 512);
        float4 wb = *(const float4*)(Wb + (size_t)k * 512 + 4);
        u64 wp[8] = {pk2(wa.x, wa.x), pk2(wa.y, wa.y), pk2(wa.z, wa.z), pk2(wa.w, wa.w),
                     pk2(wb.x, wb.x), pk2(wb.y, wb.y), pk2(wb.z, wb.z), pk2(wb.w, wb.w)};
        const float* ab = Ab + k * S34;
#pragma unroll
        for (int p = 0; p < 4; p++) {
            u64 ap = *(const u64*)(ab + 2 * p);
            if (MASKED) ap = mul2(ap, mp[p]);
#pragma unroll
            for (int c = 0; c < 8; c++) fma2(facc[p][c], ap, wp[c]);
        }
    }
}

__global__ void __launch_bounds__(256, 2)
fused_main(const float* __restrict__ img, const float* __restrict__ txt,
           const float* __restrict__ W_ie, const float* __restrict__ b_ie,
           const float* __restrict__ W_te, const float* __restrict__ b_te,
           const float* __restrict__ Wv,
           const float* __restrict__ W_ip, const float* __restrict__ b_ip,
           const float* __restrict__ W_tp, const float* __restrict__ b_tp,
           const float* __restrict__ Wc1,  const float* __restrict__ bc1,
           const float* __restrict__ Wc2,  const float* __restrict__ bc2,
           float* __restrict__ out) {
    extern __shared__ float sm[];
    float* e0T   = sm;
    float* e1T   = sm + OFF_E1;
    float* pT    = sm + OFF_PT;
    float* sAT   = sm + OFF_SAT;
    float* sattn = sm + OFF_ATTN;
    int*   sflag = (int*)(sm + OFF_FLAG);
    int*   sperm = (int*)(sm + OFF_PERM);
    int*   ssbr  = (int*)(sm + OFF_SBR);
    float* fusedT = sm;            // [512][34]
    float* h1T    = sm + OFF_PT;   // [256][34]

    const int tid = threadIdx.x;
    const int tx = tid & 31;
    const int wp = tid >> 5;       // 0..7
    const int rg = wp & 3;         // row group (8 slots = 4 pairs)
    const int nh = wp >> 2;        // N half
    const size_t row0 = (size_t)blockIdx.x * 32;

    // ---------------- P0: presence flags + branch counting sort ------------
    {
        float* npart = sAT;  // [2][32][8]
#pragma unroll
        for (int l = 0; l < 2; l++) {
            int task = tid + l * 256;
            int mod = task >> 8, r = (task >> 3) & 31, p = task & 7;
            const float* X = mod ? txt : img;
            const float4* xp = (const float4*)(X + (row0 + r) * 512 + p * 64);
            float s = 0.f;
#pragma unroll
            for (int u = 0; u < 16; u++) {
                float4 v = xp[u];
                s += v.x * v.x + v.y * v.y + v.z * v.z + v.w * v.w;
            }
            npart[task] = s;
        }
        __syncthreads();
        if (tid < 32) {
            float si = 0.f, st = 0.f;
#pragma unroll
            for (int p = 0; p < 8; p++) {
                si += npart[tid * 8 + p];
                st += npart[256 + tid * 8 + p];
            }
            int fi = si > 1e-12f, ft = st > 1e-12f;  // norm > 1e-6
            sflag[tid] = (fi && ft) ? 1 : (fi ? 2 : (ft ? 3 : 0));
        }
        __syncthreads();
        if (tid == 0) {  // counting sort: both(1), img(2), txt(3), none(0)
            int cnt[4] = {0, 0, 0, 0};
            for (int r = 0; r < 32; r++) cnt[sflag[r]]++;
            int base[4];
            base[1] = 0;
            base[2] = cnt[1];
            base[3] = cnt[1] + cnt[2];
            base[0] = cnt[1] + cnt[2] + cnt[3];
            for (int r = 0; r < 32; r++) {
                int f = sflag[r];
                int s = base[f]++;
                sperm[s] = r;
                ssbr[s]  = f;
            }
        }
        __syncthreads();
    }

    // ---------------- P1: encoders (transposed, sorted) --------------------
    for (int mod = 0; mod < 2; mod++) {
        const float* X  = mod ? txt  : img;
        const float* W  = mod ? W_te : W_ie;
        const float* bb = mod ? b_te : b_ie;
        float* eT = mod ? e1T : e0T;

        u64 acc[4][4];
#pragma unroll
        for (int p = 0; p < 4; p++)
#pragma unroll
            for (int c = 0; c < 4; c++) acc[p][c] = 0ULL;

        const float* Wb = W + nh * 128 + tx * 4;
        for (int kc = 0; kc < 512; kc += 64) {
            __syncthreads();
#pragma unroll
            for (int l = 0; l < 2; l++) {
                int idx = tid + l * 256;           // 512 float4 slots
                int s = idx >> 4, k4 = idx & 15;
                float4 v = *(const float4*)(X + (row0 + sperm[s]) * 512 + kc + k4 * 4);
                float* d = sAT + (k4 * 4) * S34 + s;
                d[0] = v.x; d[S34] = v.y; d[2 * S34] = v.z; d[3 * S34] = v.w;
            }
            __syncthreads();
#pragma unroll 4
            for (int k = 0; k < 64; k++) {
                float4 w = *(const float4*)(Wb + (size_t)(kc + k) * 256);
                u64 w0 = pk2(w.x, w.x), w1 = pk2(w.y, w.y);
                u64 w2 = pk2(w.z, w.z), w3 = pk2(w.w, w.w);
                const float* ab = sAT + k * S34 + rg * 8;
#pragma unroll
                for (int p = 0; p < 4; p++) {
                    u64 ap = *(const u64*)(ab + 2 * p);
                    fma2(acc[p][0], ap, w0);
                    fma2(acc[p][1], ap, w1);
                    fma2(acc[p][2], ap, w2);
                    fma2(acc[p][3], ap, w3);
                }
            }
        }
#pragma unroll
        for (int p = 0; p < 4; p++)
#pragma unroll
            for (int c = 0; c < 4; c++) {
                int j = nh * 128 + tx * 4 + c;
                float b = bb[j];
                float2 v = up2(acc[p][c]);
                float r0 = v.x + b, r1 = v.y + b;
                r0 = r0 > 0.f ? r0 : 0.f;
                r1 = r1 > 0.f ? r1 : 0.f;
                *(float2*)(eT + j * S34 + rg * 8 + 2 * p) = make_float2(r0, r1);
            }
    }
    __syncthreads();

    // ---------------- P2: folded attention scores + softmax ----------------
    if (tid < 128) {
        int s = tid >> 2, h = tid & 3;
        float di = 0.f, dt = 0.f;
        const float* wkp = g_wk + h * 256;
#pragma unroll 4
        for (int j = 0; j < 256; j++) {
            float w = wkp[j];
            di = fmaf(e0T[j * S34 + s], w, di);
            dt = fmaf(e1T[j * S34 + s], w, dt);
        }
        float s0 = (di + g_ck[h]) * 0.125f;
        float s1 = (dt + g_ck[h]) * 0.125f;
        float m  = fmaxf(s0, s1);
        float e0 = expf(s0 - m), e1 = expf(s1 - m);
        sattn[s * 4 + h] = e0 / (e0 + e1);  // weight on image slot
    }
    __syncthreads();

    // ---------------- P3: pooled = lerp(e1@Wv, e0@Wv, a0) ------------------
    {
        u64 q0[4][4], q1[4][4];
#pragma unroll
        for (int p = 0; p < 4; p++)
#pragma unroll
            for (int c = 0; c < 4; c++) { q0[p][c] = 0ULL; q1[p][c] = 0ULL; }

        const float* Wb = Wv + nh * 128 + tx * 4;
#pragma unroll 2
        for (int k = 0; k < 256; k++) {
            float4 w = *(const float4*)(Wb + (size_t)k * 256);
            u64 w0 = pk2(w.x, w.x), w1 = pk2(w.y, w.y);
            u64 w2 = pk2(w.z, w.z), w3 = pk2(w.w, w.w);
            const float* a0b = e0T + k * S34 + rg * 8;
            const float* a1b = e1T + k * S34 + rg * 8;
#pragma unroll
            for (int p = 0; p < 4; p++) {
                u64 ap0 = *(const u64*)(a0b + 2 * p);
                u64 ap1 = *(const u64*)(a1b + 2 * p);
                fma2(q0[p][0], ap0, w0); fma2(q1[p][0], ap1, w0);
                fma2(q0[p][1], ap0, w1); fma2(q1[p][1], ap1, w1);
                fma2(q0[p][2], ap0, w2); fma2(q1[p][2], ap1, w2);
                fma2(q0[p][3], ap0, w3); fma2(q1[p][3], ap1, w3);
            }
        }
#pragma unroll
        for (int p = 0; p < 4; p++) {
            int s0 = rg * 8 + 2 * p;
#pragma unroll
            for (int c = 0; c < 4; c++) {
                int j = nh * 128 + tx * 4 + c;
                int h = j >> 6;
                float a00 = sattn[s0 * 4 + h], a01 = sattn[(s0 + 1) * 4 + h];
                float2 v0 = up2(q0[p][c]), v1 = up2(q1[p][c]);
                float r0 = fmaf(a00, v0.x - v1.x, v1.x);
                float r1 = fmaf(a01, v0.y - v1.y, v1.y);
                *(float2*)(pT + j * S34 + s0) = make_float2(r0, r1);
            }
        }
    }
    __syncthreads();

    // ---------------- P5: branch-specialized projection GEMM ---------------
    {
        u64 facc[4][8];
#pragma unroll
        for (int p = 0; p < 4; p++)
#pragma unroll
            for (int c = 0; c < 8; c++) facc[p][c] = 0ULL;

        int br[8];
#pragma unroll
        for (int i = 0; i < 8; i++) br[i] = ssbr[rg * 8 + i];

        if (br[0] == br[7]) {
            if (br[0] == 1)      gemm_seg<false>(facc, pT,  g_Wof, 0, rg, nh, tx);
            else if (br[0] == 2) gemm_seg<false>(facc, e0T, W_ip,  0, rg, nh, tx);
            else if (br[0] == 3) gemm_seg<false>(facc, e1T, W_tp,  0, rg, nh, tx);
        } else {
            unsigned need = 0;
#pragma unroll
            for (int i = 0; i < 8; i++) need |= 1u << br[i];
            for (int seg = 1; seg <= 3; seg++) {
                if (!(need & (1u << seg))) continue;
                u64 mp[4];
#pragma unroll
                for (int p = 0; p < 4; p++)
                    mp[p] = pk2(br[2 * p] == seg ? 1.f : 0.f,
                                br[2 * p + 1] == seg ? 1.f : 0.f);
                const float* A = (seg == 1) ? pT : (seg == 2) ? e0T : e1T;
                const float* W = (seg == 1) ? g_Wof : (seg == 2) ? W_ip : W_tp;
                gemm_seg<true>(facc, A, W, mp, rg, nh, tx);
            }
        }
        __syncthreads();  // all smem reads done before fusedT overlay write
#pragma unroll
        for (int p = 0; p < 4; p++) {
            int s0 = rg * 8 + 2 * p;
            int f0 = ssbr[s0], f1 = ssbr[s0 + 1];
            const float* b0p = (f0 == 1) ? g_bof : (f0 == 2) ? b_ip
                             : (f0 == 3) ? b_tp : (const float*)0;
            const float* b1p = (f1 == 1) ? g_bof : (f1 == 2) ? b_ip
                             : (f1 == 3) ? b_tp : (const float*)0;
#pragma unroll
            for (int c = 0; c < 8; c++) {
                int j = nh * 256 + tx * 8 + c;
                float2 v = up2(facc[p][c]);
                float r0 = v.x + (b0p ? b0p[j] : 0.f);
                float r1 = v.y + (b1p ? b1p[j] : 0.f);
                *(float2*)(fusedT + j * S34 + s0) = make_float2(r0, r1);
            }
        }
        __syncthreads();
    }

    // ---------------- P6: classifier layer 1 (512 -> 256, ReLU) ------------
    {
        u64 cacc[4][4];
#pragma unroll
        for (int p = 0; p < 4; p++)
#pragma unroll
            for (int c = 0; c < 4; c++) cacc[p][c] = 0ULL;

        const float* Wb = Wc1 + nh * 128 + tx * 4;
#pragma unroll 4
        for (int k = 0; k < 512; k++) {
            float4 w = *(const float4*)(Wb + (size_t)k * 256);
            u64 w0 = pk2(w.x, w.x), w1 = pk2(w.y, w.y);
            u64 w2 = pk2(w.z, w.z), w3 = pk2(w.w, w.w);
            const float* ab = fusedT + k * S34 + rg * 8;
#pragma unroll
            for (int p = 0; p < 4; p++) {
                u64 ap = *(const u64*)(ab + 2 * p);
                fma2(cacc[p][0], ap, w0);
                fma2(cacc[p][1], ap, w1);
                fma2(cacc[p][2], ap, w2);
                fma2(cacc[p][3], ap, w3);
            }
        }
        __syncthreads();  // fusedT reads done before h1T overlay write (pT dead)
#pragma unroll
        for (int p = 0; p < 4; p++)
#pragma unroll
            for (int c = 0; c < 4; c++) {
                int j = nh * 128 + tx * 4 + c;
                float b = bc1[j];
                float2 v = up2(cacc[p][c]);
                float r0 = v.x + b, r1 = v.y + b;
                r0 = r0 > 0.f ? r0 : 0.f;
                r1 = r1 > 0.f ? r1 : 0.f;
                *(float2*)(h1T + j * S34 + rg * 8 + 2 * p) = make_float2(r0, r1);
            }
        __syncthreads();
    }

    // ---------------- P7: classifier layer 2 (256 -> 80) -------------------
    if (nh == 0) {
        u64 lacc[4][2];
#pragma unroll
        for (int p = 0; p < 4; p++) { lacc[p][0] = 0ULL; lacc[p][1] = 0ULL; }
#pragma unroll 2
        for (int k = 0; k < 256; k++) {
            float2 w = *(const float2*)(Wc2 + (size_t)k * 80 + tx * 2);
            u64 w0 = pk2(w.x, w.x), w1 = pk2(w.y, w.y);
            const float* ab = h1T + k * S34 + rg * 8;
#pragma unroll
            for (int p = 0; p < 4; p++) {
                u64 ap = *(const u64*)(ab + 2 * p);
                fma2(lacc[p][0], ap, w0);
                fma2(lacc[p][1], ap, w1);
            }
        }
#pragma unroll
        for (int p = 0; p < 4; p++) {
            int s0 = rg * 8 + 2 * p;
            size_t r0o = (row0 + sperm[s0]) * 80;
            size_t r1o = (row0 + sperm[s0 + 1]) * 80;
#pragma unroll
            for (int c = 0; c < 2; c++) {
                int j = tx * 2 + c;
                float2 v = up2(lacc[p][c]);
                out[r0o + j] = v.x + bc2[j];
                out[r1o + j] = v.y + bc2[j];
            }
        }
    } else {
        u64 lacc[4];
#pragma unroll
        for (int p = 0; p < 4; p++) lacc[p] = 0ULL;
#pragma unroll 2
        for (int k = 0; k < 256; k++) {
            float w = (tx < 16) ? Wc2[(size_t)k * 80 + 64 + tx] : 0.f;
            u64 w0 = pk2(w, w);
            const float* ab = h1T + k * S34 + rg * 8;
#pragma unroll
            for (int p = 0; p < 4; p++) {
                u64 ap = *(const u64*)(ab + 2 * p);
                fma2(lacc[p], ap, w0);
            }
        }
        if (tx < 16) {
            int j = 64 + tx;
#pragma unroll
            for (int p = 0; p < 4; p++) {
                int s0 = rg * 8 + 2 * p;
                float2 v = up2(lacc[p]);
                out[(row0 + sperm[s0]) * 80 + j]     = v.x + bc2[j];
                out[(row0 + sperm[s0 + 1]) * 80 + j] = v.y + bc2[j];
            }
        }
    }
}

// ------------------------------- launch ------------------------------------

extern "C" void kernel_launch(void* const* d_in, const int* in_sizes, int n_in,
                              void* d_out, int out_size) {
    const float* img  = (const float*)d_in[0];
    const float* txt  = (const float*)d_in[1];
    const float* W_ie = (const float*)d_in[2];
    const float* b_ie = (const float*)d_in[3];
    const float* W_te = (const float*)d_in[4];
    const float* b_te = (const float*)d_in[5];
    const float* fq   = (const float*)d_in[6];
    const float* Wq   = (const float*)d_in[7];
    const float* bq   = (const float*)d_in[8];
    const float* Wk   = (const float*)d_in[9];
    const float* bk   = (const float*)d_in[10];
    const float* Wv   = (const float*)d_in[11];
    const float* bv   = (const float*)d_in[12];
    const float* Wo   = (const float*)d_in[13];
    const float* bo   = (const float*)d_in[14];
    const float* W_ip = (const float*)d_in[15];
    const float* b_ip = (const float*)d_in[16];
    const float* W_tp = (const float*)d_in[17];
    const float* b_tp = (const float*)d_in[18];
    const float* W_fp = (const float*)d_in[19];
    const float* b_fp = (const float*)d_in[20];
    const float* Wc1  = (const float*)d_in[21];
    const float* bc1  = (const float*)d_in[22];
    const float* Wc2  = (const float*)d_in[23];
    const float* bc2  = (const float*)d_in[24];
    float* out = (float*)d_out;

    const int B = in_sizes[0] / 512;

    setup_all<<<17, 256>>>(fq, Wq, bq, Wk, bk, bv, Wo, bo, W_fp, b_fp);

    cudaFuncSetAttribute(fused_main, cudaFuncAttributeMaxDynamicSharedMemorySize,
                         SMEM_BYTES);
    fused_main<<<B / 32, 256, SMEM_BYTES>>>(
        img, txt, W_ie, b_ie, W_te, b_te, Wv,
        W_ip, b_ip, W_tp, b_tp, Wc1, bc1, Wc2, bc2, out);
}

// round 8
// speedup vs baseline: 1.0016x; 1.0016x over previous
#include <cuda_runtime.h>
#include <math.h>

// ---------------------------------------------------------------------------
// AECFModel fused multimodal classifier — fp32, row-pair f32x2 FMA on
// transposed smem tiles, pre-sorted branches, 2 CTAs/SM x 256 thr x 32 rows.
// H=256, ID=TD=512, NC=80, B=131072.
// ---------------------------------------------------------------------------

typedef unsigned long long u64;

__device__ __forceinline__ u64 pk2(float x, float y) {
    u64 r; asm("mov.b64 %0,{%1,%2};" : "=l"(r) : "f"(x), "f"(y)); return r;
}
__device__ __forceinline__ void fma2(u64& d, u64 a, u64 b) {
    asm("fma.rn.f32x2 %0,%1,%2,%0;" : "+l"(d) : "l"(a), "l"(b));
}
__device__ __forceinline__ u64 mul2(u64 a, u64 b) {
    u64 r; asm("mul.rn.f32x2 %0,%1,%2;" : "=l"(r) : "l"(a), "l"(b)); return r;
}
__device__ __forceinline__ float2 up2(u64 d) {
    float2 r; asm("mov.b64 {%0,%1},%2;" : "=f"(r.x), "=f"(r.y) : "l"(d)); return r;
}

// Per-launch precomputed tensors (device-global scratch; rewritten every call).
__device__ float g_q[256];
__device__ float g_wk[4 * 256];
__device__ float g_ck[4];
__device__ float g_tmp[256];
__device__ float g_Wof[256 * 512];  // Wo @ W_fp
__device__ float g_bof[512];        // (bv@Wo+bo) @ W_fp + b_fp

// ---------------------------- combined setup -------------------------------
// grid 17 x 256. Block 0: small precomputes. Blocks 1..16: Wof tiles.
__global__ void setup_all(const float* __restrict__ fq, const float* __restrict__ Wq,
                          const float* __restrict__ bq, const float* __restrict__ Wk,
                          const float* __restrict__ bk, const float* __restrict__ bv,
                          const float* __restrict__ Wo, const float* __restrict__ bo,
                          const float* __restrict__ Wfp, const float* __restrict__ bfp) {
    __shared__ float sA[64 * 65];
    int t = threadIdx.x;
    if (blockIdx.x == 0) {
        {   // g_q
            float s = bq[t];
#pragma unroll 8
            for (int k = 0; k < 256; k++) s = fmaf(fq[k], Wq[k * 256 + t], s);
            g_q[t] = s;
        }
        __syncthreads();
#pragma unroll
        for (int l = 0; l < 4; l++) {   // g_wk
            int idx = t + l * 256;
            int h = idx >> 8, j = idx & 255;
            float s = 0.f;
#pragma unroll 8
            for (int d = 0; d < 64; d++)
                s = fmaf(Wk[j * 256 + h * 64 + d], g_q[h * 64 + d], s);
            g_wk[h * 256 + j] = s;
        }
        if (t < 4) {                    // g_ck
            float c = 0.f;
#pragma unroll 8
            for (int d = 0; d < 64; d++) c = fmaf(bk[t * 64 + d], g_q[t * 64 + d], c);
            g_ck[t] = c;
        }
        __syncthreads();
        {   // g_tmp = bv@Wo + bo
            float s = bo[t];
#pragma unroll 8
            for (int k = 0; k < 256; k++) s = fmaf(bv[k], Wo[k * 256 + t], s);
            g_tmp[t] = s;
        }
        __syncthreads();
#pragma unroll
        for (int l = 0; l < 2; l++) {   // g_bof
            int j = t + l * 256;
            float s = bfp[j];
#pragma unroll 8
            for (int m = 0; m < 256; m++) s = fmaf(g_tmp[m], Wfp[m * 512 + j], s);
            g_bof[j] = s;
        }
        return;
    }
    // ---- Wof tile ----
    int bid = blockIdx.x - 1;
    int tx = t & 31, ty = t >> 5;
    int it = bid >> 2, jt = bid & 3;
    float acc[8][4];
#pragma unroll
    for (int i = 0; i < 8; i++)
#pragma unroll
        for (int c = 0; c < 4; c++) acc[i][c] = 0.f;

    for (int mc = 0; mc < 256; mc += 64) {
        __syncthreads();
#pragma unroll
        for (int l = 0; l < 16; l++) {
            int idx = t + l * 256;
            int r = idx >> 6, k = idx & 63;
            sA[r * 65 + k] = Wo[(it * 64 + r) * 256 + mc + k];
        }
        __syncthreads();
#pragma unroll 2
        for (int k = 0; k < 64; k++) {
            const float* Wp = Wfp + (size_t)(mc + k) * 512 + jt * 128 + tx;
            float w[4];
#pragma unroll
            for (int c = 0; c < 4; c++) w[c] = Wp[c * 32];
#pragma unroll
            for (int i = 0; i < 8; i++) {
                float a = sA[(ty * 8 + i) * 65 + k];
#pragma unroll
                for (int c = 0; c < 4; c++) acc[i][c] = fmaf(a, w[c], acc[i][c]);
            }
        }
    }
    __syncthreads();
#pragma unroll
    for (int i = 0; i < 8; i++)
#pragma unroll
        for (int c = 0; c < 4; c++)
            g_Wof[(size_t)(it * 64 + ty * 8 + i) * 512 + jt * 128 + tx + 32 * c] =
                acc[i][c];
}

// ------------------------------- main kernel -------------------------------
// 32 rows/CTA (sorted slots), 256 threads (8 warps), 2 CTAs/SM.
// warp w: rg = w&3 (slots rg*8..+7 as 4 row-pairs), nh = w>>2 (N half).
// All smem tensors transposed [k][slot], stride 34 (even -> LDS.64 pairs).
//
// smem (float offsets):
//   e0T @ 0     [256][34]   e1T @ 8704 [256][34]   pT @ 17408 [256][34]
//   sAT @ 26112 [64][34] staging (also norm partials pre-pass)
//   attn @ 28288 [32][4]   flag @ 28416  perm @ 28448  sbr @ 28480
//   overlays: fusedT @ 0 [512][34] (= e0T+e1T exactly), h1T @ 17408 [256][34]

#define S34 34
#define OFF_E1   8704
#define OFF_PT   17408
#define OFF_SAT  26112
#define OFF_ATTN 28288
#define OFF_FLAG 28416
#define OFF_PERM 28448
#define OFF_SBR  28480
#define SMEM_FLOATS 28512
#define SMEM_BYTES (SMEM_FLOATS * 4)

// P5 segment: K=256 -> this thread's 8 cols (nh*256 + tx*8). Row-pair A from AT.
template <bool MASKED>
__device__ __forceinline__ void gemm_seg(u64 (&facc)[4][8],
                                         const float* __restrict__ AT,
                                         const float* __restrict__ W,
                                         const u64* mp, int rg, int nh, int tx) {
    const float* Wb = W + nh * 256 + tx * 8;
    const float* Ab = AT + rg * 8;
#pragma unroll 2
    for (int k = 0; k < 256; k++) {
        float4 wa = *(const float4*)(Wb + (size_t)k * 512);
        float4 wb = *(const float4*)(Wb + (size_t)k * 512 + 4);
        u64 wp[8] = {pk2(wa.x, wa.x), pk2(wa.y, wa.y), pk2(wa.z, wa.z), pk2(wa.w, wa.w),
                     pk2(wb.x, wb.x), pk2(wb.y, wb.y), pk2(wb.z, wb.z), pk2(wb.w, wb.w)};
        const float* ab = Ab + k * S34;
#pragma unroll
        for (int p = 0; p < 4; p++) {
            u64 ap = *(const u64*)(ab + 2 * p);
            if (MASKED) ap = mul2(ap, mp[p]);
#pragma unroll
            for (int c = 0; c < 8; c++) fma2(facc[p][c], ap, wp[c]);
        }
    }
}

__global__ void __launch_bounds__(256, 2)
fused_main(const float* __restrict__ img, const float* __restrict__ txt,
           const float* __restrict__ W_ie, const float* __restrict__ b_ie,
           const float* __restrict__ W_te, const float* __restrict__ b_te,
           const float* __restrict__ Wv,
           const float* __restrict__ W_ip, const float* __restrict__ b_ip,
           const float* __restrict__ W_tp, const float* __restrict__ b_tp,
           const float* __restrict__ Wc1,  const float* __restrict__ bc1,
           const float* __restrict__ Wc2,  const float* __restrict__ bc2,
           float* __restrict__ out) {
    extern __shared__ float sm[];
    float* e0T   = sm;
    float* e1T   = sm + OFF_E1;
    float* pT    = sm + OFF_PT;
    float* sAT   = sm + OFF_SAT;
    float* sattn = sm + OFF_ATTN;
    int*   sflag = (int*)(sm + OFF_FLAG);
    int*   sperm = (int*)(sm + OFF_PERM);
    int*   ssbr  = (int*)(sm + OFF_SBR);
    float* fusedT = sm;            // [512][34]
    float* h1T    = sm + OFF_PT;   // [256][34]

    const int tid = threadIdx.x;
    const int tx = tid & 31;
    const int wp = tid >> 5;       // 0..7
    const int rg = wp & 3;         // row group (8 slots = 4 pairs)
    const int nh = wp >> 2;        // N half
    const size_t row0 = (size_t)blockIdx.x * 32;

    // ---------------- P0: presence flags + branch counting sort ------------
    {
        float* npart = sAT;  // [2][32][8]
#pragma unroll
        for (int l = 0; l < 2; l++) {
            int task = tid + l * 256;
            int mod = task >> 8, r = (task >> 3) & 31, p = task & 7;
            const float* X = mod ? txt : img;
            const float4* xp = (const float4*)(X + (row0 + r) * 512 + p * 64);
            float s = 0.f;
#pragma unroll
            for (int u = 0; u < 16; u++) {
                float4 v = xp[u];
                s += v.x * v.x + v.y * v.y + v.z * v.z + v.w * v.w;
            }
            npart[task] = s;
        }
        __syncthreads();
        if (tid < 32) {
            float si = 0.f, st = 0.f;
#pragma unroll
            for (int p = 0; p < 8; p++) {
                si += npart[tid * 8 + p];
                st += npart[256 + tid * 8 + p];
            }
            int fi = si > 1e-12f, ft = st > 1e-12f;  // norm > 1e-6
            sflag[tid] = (fi && ft) ? 1 : (fi ? 2 : (ft ? 3 : 0));
        }
        __syncthreads();
        if (tid == 0) {  // counting sort: both(1), img(2), txt(3), none(0)
            int cnt[4] = {0, 0, 0, 0};
            for (int r = 0; r < 32; r++) cnt[sflag[r]]++;
            int base[4];
            base[1] = 0;
            base[2] = cnt[1];
            base[3] = cnt[1] + cnt[2];
            base[0] = cnt[1] + cnt[2] + cnt[3];
            for (int r = 0; r < 32; r++) {
                int f = sflag[r];
                int s = base[f]++;
                sperm[s] = r;
                ssbr[s]  = f;
            }
        }
        __syncthreads();
    }

    // ---------------- P1: encoders (transposed, sorted) --------------------
    for (int mod = 0; mod < 2; mod++) {
        const float* X  = mod ? txt  : img;
        const float* W  = mod ? W_te : W_ie;
        const float* bb = mod ? b_te : b_ie;
        float* eT = mod ? e1T : e0T;

        u64 acc[4][4];
#pragma unroll
        for (int p = 0; p < 4; p++)
#pragma unroll
            for (int c = 0; c < 4; c++) acc[p][c] = 0ULL;

        const float* Wb = W + nh * 128 + tx * 4;
        for (int kc = 0; kc < 512; kc += 64) {
            __syncthreads();
#pragma unroll
            for (int l = 0; l < 2; l++) {
                int idx = tid + l * 256;           // 512 float4 slots
                int s = idx >> 4, k4 = idx & 15;
                float4 v = *(const float4*)(X + (row0 + sperm[s]) * 512 + kc + k4 * 4);
                float* d = sAT + (k4 * 4) * S34 + s;
                d[0] = v.x; d[S34] = v.y; d[2 * S34] = v.z; d[3 * S34] = v.w;
            }
            __syncthreads();
#pragma unroll 4
            for (int k = 0; k < 64; k++) {
                float4 w = *(const float4*)(Wb + (size_t)(kc + k) * 256);
                u64 w0 = pk2(w.x, w.x), w1 = pk2(w.y, w.y);
                u64 w2 = pk2(w.z, w.z), w3 = pk2(w.w, w.w);
                const float* ab = sAT + k * S34 + rg * 8;
#pragma unroll
                for (int p = 0; p < 4; p++) {
                    u64 ap = *(const u64*)(ab + 2 * p);
                    fma2(acc[p][0], ap, w0);
                    fma2(acc[p][1], ap, w1);
                    fma2(acc[p][2], ap, w2);
                    fma2(acc[p][3], ap, w3);
                }
            }
        }
#pragma unroll
        for (int p = 0; p < 4; p++)
#pragma unroll
            for (int c = 0; c < 4; c++) {
                int j = nh * 128 + tx * 4 + c;
                float b = bb[j];
                float2 v = up2(acc[p][c]);
                float r0 = v.x + b, r1 = v.y + b;
                r0 = r0 > 0.f ? r0 : 0.f;
                r1 = r1 > 0.f ? r1 : 0.f;
                *(float2*)(eT + j * S34 + rg * 8 + 2 * p) = make_float2(r0, r1);
            }
    }
    __syncthreads();

    // ---------------- P2: folded attention scores + softmax ----------------
    if (tid < 128) {
        int s = tid >> 2, h = tid & 3;
        float di = 0.f, dt = 0.f;
        const float* wkp = g_wk + h * 256;
#pragma unroll 4
        for (int j = 0; j < 256; j++) {
            float w = wkp[j];
            di = fmaf(e0T[j * S34 + s], w, di);
            dt = fmaf(e1T[j * S34 + s], w, dt);
        }
        float s0 = (di + g_ck[h]) * 0.125f;
        float s1 = (dt + g_ck[h]) * 0.125f;
        float m  = fmaxf(s0, s1);
        float e0 = expf(s0 - m), e1 = expf(s1 - m);
        sattn[s * 4 + h] = e0 / (e0 + e1);  // weight on image slot
    }
    __syncthreads();

    // ---------------- P3: pooled = lerp(e1@Wv, e0@Wv, a0) ------------------
    {
        u64 q0[4][4], q1[4][4];
#pragma unroll
        for (int p = 0; p < 4; p++)
#pragma unroll
            for (int c = 0; c < 4; c++) { q0[p][c] = 0ULL; q1[p][c] = 0ULL; }

        const float* Wb = Wv + nh * 128 + tx * 4;
#pragma unroll 2
        for (int k = 0; k < 256; k++) {
            float4 w = *(const float4*)(Wb + (size_t)k * 256);
            u64 w0 = pk2(w.x, w.x), w1 = pk2(w.y, w.y);
            u64 w2 = pk2(w.z, w.z), w3 = pk2(w.w, w.w);
            const float* a0b = e0T + k * S34 + rg * 8;
            const float* a1b = e1T + k * S34 + rg * 8;
#pragma unroll
            for (int p = 0; p < 4; p++) {
                u64 ap0 = *(const u64*)(a0b + 2 * p);
                u64 ap1 = *(const u64*)(a1b + 2 * p);
                fma2(q0[p][0], ap0, w0); fma2(q1[p][0], ap1, w0);
                fma2(q0[p][1], ap0, w1); fma2(q1[p][1], ap1, w1);
                fma2(q0[p][2], ap0, w2); fma2(q1[p][2], ap1, w2);
                fma2(q0[p][3], ap0, w3); fma2(q1[p][3], ap1, w3);
            }
        }
#pragma unroll
        for (int p = 0; p < 4; p++) {
            int s0 = rg * 8 + 2 * p;
#pragma unroll
            for (int c = 0; c < 4; c++) {
                int j = nh * 128 + tx * 4 + c;
                int h = j >> 6;
                float a00 = sattn[s0 * 4 + h], a01 = sattn[(s0 + 1) * 4 + h];
                float2 v0 = up2(q0[p][c]), v1 = up2(q1[p][c]);
                float r0 = fmaf(a00, v0.x - v1.x, v1.x);
                float r1 = fmaf(a01, v0.y - v1.y, v1.y);
                *(float2*)(pT + j * S34 + s0) = make_float2(r0, r1);
            }
        }
    }
    __syncthreads();

    // ---------------- P5: branch-specialized projection GEMM ---------------
    {
        u64 facc[4][8];
#pragma unroll
        for (int p = 0; p < 4; p++)
#pragma unroll
            for (int c = 0; c < 8; c++) facc[p][c] = 0ULL;

        int br[8];
#pragma unroll
        for (int i = 0; i < 8; i++) br[i] = ssbr[rg * 8 + i];

        if (br[0] == br[7]) {
            if (br[0] == 1)      gemm_seg<false>(facc, pT,  g_Wof, 0, rg, nh, tx);
            else if (br[0] == 2) gemm_seg<false>(facc, e0T, W_ip,  0, rg, nh, tx);
            else if (br[0] == 3) gemm_seg<false>(facc, e1T, W_tp,  0, rg, nh, tx);
        } else {
            unsigned need = 0;
#pragma unroll
            for (int i = 0; i < 8; i++) need |= 1u << br[i];
            for (int seg = 1; seg <= 3; seg++) {
                if (!(need & (1u << seg))) continue;
                u64 mp[4];
#pragma unroll
                for (int p = 0; p < 4; p++)
                    mp[p] = pk2(br[2 * p] == seg ? 1.f : 0.f,
                                br[2 * p + 1] == seg ? 1.f : 0.f);
                const float* A = (seg == 1) ? pT : (seg == 2) ? e0T : e1T;
                const float* W = (seg == 1) ? g_Wof : (seg == 2) ? W_ip : W_tp;
                gemm_seg<true>(facc, A, W, mp, rg, nh, tx);
            }
        }
        __syncthreads();  // all smem reads done before fusedT overlay write
#pragma unroll
        for (int p = 0; p < 4; p++) {
            int s0 = rg * 8 + 2 * p;
            int f0 = ssbr[s0], f1 = ssbr[s0 + 1];
            const float* b0p = (f0 == 1) ? g_bof : (f0 == 2) ? b_ip
                             : (f0 == 3) ? b_tp : (const float*)0;
            const float* b1p = (f1 == 1) ? g_bof : (f1 == 2) ? b_ip
                             : (f1 == 3) ? b_tp : (const float*)0;
#pragma unroll
            for (int c = 0; c < 8; c++) {
                int j = nh * 256 + tx * 8 + c;
                float2 v = up2(facc[p][c]);
                float r0 = v.x + (b0p ? b0p[j] : 0.f);
                float r1 = v.y + (b1p ? b1p[j] : 0.f);
                *(float2*)(fusedT + j * S34 + s0) = make_float2(r0, r1);
            }
        }
        __syncthreads();
    }

    // ---------------- P6: classifier layer 1 (512 -> 256, ReLU) ------------
    {
        u64 cacc[4][4];
#pragma unroll
        for (int p = 0; p < 4; p++)
#pragma unroll
            for (int c = 0; c < 4; c++) cacc[p][c] = 0ULL;

        const float* Wb = Wc1 + nh * 128 + tx * 4;
#pragma unroll 4
        for (int k = 0; k < 512; k++) {
            float4 w = *(const float4*)(Wb + (size_t)k * 256);
            u64 w0 = pk2(w.x, w.x), w1 = pk2(w.y, w.y);
            u64 w2 = pk2(w.z, w.z), w3 = pk2(w.w, w.w);
            const float* ab = fusedT + k * S34 + rg * 8;
#pragma unroll
            for (int p = 0; p < 4; p++) {
                u64 ap = *(const u64*)(ab + 2 * p);
                fma2(cacc[p][0], ap, w0);
                fma2(cacc[p][1], ap, w1);
                fma2(cacc[p][2], ap, w2);
                fma2(cacc[p][3], ap, w3);
            }
        }
        __syncthreads();  // fusedT reads done before h1T overlay write (pT dead)
#pragma unroll
        for (int p = 0; p < 4; p++)
#pragma unroll
            for (int c = 0; c < 4; c++) {
                int j = nh * 128 + tx * 4 + c;
                float b = bc1[j];
                float2 v = up2(cacc[p][c]);
                float r0 = v.x + b, r1 = v.y + b;
                r0 = r0 > 0.f ? r0 : 0.f;
                r1 = r1 > 0.f ? r1 : 0.f;
                *(float2*)(h1T + j * S34 + rg * 8 + 2 * p) = make_float2(r0, r1);
            }
        __syncthreads();
    }

    // ---------------- P7: classifier layer 2 (256 -> 80) -------------------
    if (nh == 0) {
        u64 lacc[4][2];
#pragma unroll
        for (int p = 0; p < 4; p++) { lacc[p][0] = 0ULL; lacc[p][1] = 0ULL; }
#pragma unroll 2
        for (int k = 0; k < 256; k++) {
            float2 w = *(const float2*)(Wc2 + (size_t)k * 80 + tx * 2);
            u64 w0 = pk2(w.x, w.x), w1 = pk2(w.y, w.y);
            const float* ab = h1T + k * S34 + rg * 8;
#pragma unroll
            for (int p = 0; p < 4; p++) {
                u64 ap = *(const u64*)(ab + 2 * p);
                fma2(lacc[p][0], ap, w0);
                fma2(lacc[p][1], ap, w1);
            }
        }
#pragma unroll
        for (int p = 0; p < 4; p++) {
            int s0 = rg * 8 + 2 * p;
            size_t r0o = (row0 + sperm[s0]) * 80;
            size_t r1o = (row0 + sperm[s0 + 1]) * 80;
#pragma unroll
            for (int c = 0; c < 2; c++) {
                int j = tx * 2 + c;
                float2 v = up2(lacc[p][c]);
                out[r0o + j] = v.x + bc2[j];
                out[r1o + j] = v.y + bc2[j];
            }
        }
    } else {
        u64 lacc[4];
#pragma unroll
        for (int p = 0; p < 4; p++) lacc[p] = 0ULL;
#pragma unroll 2
        for (int k = 0; k < 256; k++) {
            float w = (tx < 16) ? Wc2[(size_t)k * 80 + 64 + tx] : 0.f;
            u64 w0 = pk2(w, w);
            const float* ab = h1T + k * S34 + rg * 8;
#pragma unroll
            for (int p = 0; p < 4; p++) {
                u64 ap = *(const u64*)(ab + 2 * p);
                fma2(lacc[p], ap, w0);
            }
        }
        if (tx < 16) {
            int j = 64 + tx;
#pragma unroll
            for (int p = 0; p < 4; p++) {
                int s0 = rg * 8 + 2 * p;
                float2 v = up2(lacc[p]);
                out[(row0 + sperm[s0]) * 80 + j]     = v.x + bc2[j];
                out[(row0 + sperm[s0 + 1]) * 80 + j] = v.y + bc2[j];
            }
        }
    }
}

// ------------------------------- launch ------------------------------------

extern "C" void kernel_launch(void* const* d_in, const int* in_sizes, int n_in,
                              void* d_out, int out_size) {
    const float* img  = (const float*)d_in[0];
    const float* txt  = (const float*)d_in[1];
    const float* W_ie = (const float*)d_in[2];
    const float* b_ie = (const float*)d_in[3];
    const float* W_te = (const float*)d_in[4];
    const float* b_te = (const float*)d_in[5];
    const float* fq   = (const float*)d_in[6];
    const float* Wq   = (const float*)d_in[7];
    const float* bq   = (const float*)d_in[8];
    const float* Wk   = (const float*)d_in[9];
    const float* bk   = (const float*)d_in[10];
    const float* Wv   = (const float*)d_in[11];
    const float* bv   = (const float*)d_in[12];
    const float* Wo   = (const float*)d_in[13];
    const float* bo   = (const float*)d_in[14];
    const float* W_ip = (const float*)d_in[15];
    const float* b_ip = (const float*)d_in[16];
    const float* W_tp = (const float*)d_in[17];
    const float* b_tp = (const float*)d_in[18];
    const float* W_fp = (const float*)d_in[19];
    const float* b_fp = (const float*)d_in[20];
    const float* Wc1  = (const float*)d_in[21];
    const float* bc1  = (const float*)d_in[22];
    const float* Wc2  = (const float*)d_in[23];
    const float* bc2  = (const float*)d_in[24];
    float* out = (float*)d_out;

    const int B = in_sizes[0] / 512;

    setup_all<<<17, 256>>>(fq, Wq, bq, Wk, bk, bv, Wo, bo, W_fp, b_fp);

    cudaFuncSetAttribute(fused_main, cudaFuncAttributeMaxDynamicSharedMemorySize,
                         SMEM_BYTES);
    fused_main<<<B / 32, 256, SMEM_BYTES>>>(
        img, txt, W_ie, b_ie, W_te, b_te, Wv,
        W_ip, b_ip, W_tp, b_tp, Wc1, bc1, Wc2, bc2, out);
}

// round 9
// speedup vs baseline: 1.3263x; 1.3241x over previous
#include <cuda_runtime.h>
#include <math.h>

// ---------------------------------------------------------------------------
// AECFModel — fp32 f32x2, transposed smem tiles, pre-sorted branches,
// P5+P6 folded via W5c = W5_branch @ Wc1, warp-level dead-GEMM skips.
// H=256, ID=TD=512, NC=80, B=131072.
// ---------------------------------------------------------------------------

typedef unsigned long long u64;

__device__ __forceinline__ u64 pk2(float x, float y) {
    u64 r; asm("mov.b64 %0,{%1,%2};" : "=l"(r) : "f"(x), "f"(y)); return r;
}
__device__ __forceinline__ void fma2(u64& d, u64 a, u64 b) {
    asm("fma.rn.f32x2 %0,%1,%2,%0;" : "+l"(d) : "l"(a), "l"(b));
}
__device__ __forceinline__ u64 mul2(u64 a, u64 b) {
    u64 r; asm("mul.rn.f32x2 %0,%1,%2;" : "=l"(r) : "l"(a), "l"(b)); return r;
}
__device__ __forceinline__ float2 up2(u64 d) {
    float2 r; asm("mov.b64 {%0,%1},%2;" : "=f"(r.x), "=f"(r.y) : "l"(d)); return r;
}

// Per-launch precomputed tensors (device-global scratch; rewritten every call).
__device__ float g_q[256];
__device__ float g_wk[4 * 256];
__device__ float g_ck[4];
__device__ float g_tmp[256];
__device__ float g_Wof[256 * 512];   // Wo @ W_fp
__device__ float g_bof[512];         // (bv@Wo+bo) @ W_fp + b_fp
__device__ float g_W5c[3 * 256 * 256]; // {Wof,W_ip,W_tp} @ Wc1
__device__ float g_b5c[3 * 256];       // {g_bof,b_ip,b_tp} @ Wc1 + bc1

// ---------------------------- setup kernel 1 --------------------------------
// grid 17 x 256. Block 0: small precomputes. Blocks 1..16: Wof tiles.
__global__ void setup_all(const float* __restrict__ fq, const float* __restrict__ Wq,
                          const float* __restrict__ bq, const float* __restrict__ Wk,
                          const float* __restrict__ bk, const float* __restrict__ bv,
                          const float* __restrict__ Wo, const float* __restrict__ bo,
                          const float* __restrict__ Wfp, const float* __restrict__ bfp) {
    __shared__ float sA[64 * 65];
    int t = threadIdx.x;
    if (blockIdx.x == 0) {
        {   // g_q
            float s = bq[t];
#pragma unroll 8
            for (int k = 0; k < 256; k++) s = fmaf(fq[k], Wq[k * 256 + t], s);
            g_q[t] = s;
        }
        __syncthreads();
#pragma unroll
        for (int l = 0; l < 4; l++) {   // g_wk
            int idx = t + l * 256;
            int h = idx >> 8, j = idx & 255;
            float s = 0.f;
#pragma unroll 8
            for (int d = 0; d < 64; d++)
                s = fmaf(Wk[j * 256 + h * 64 + d], g_q[h * 64 + d], s);
            g_wk[h * 256 + j] = s;
        }
        if (t < 4) {                    // g_ck
            float c = 0.f;
#pragma unroll 8
            for (int d = 0; d < 64; d++) c = fmaf(bk[t * 64 + d], g_q[t * 64 + d], c);
            g_ck[t] = c;
        }
        __syncthreads();
        {   // g_tmp = bv@Wo + bo
            float s = bo[t];
#pragma unroll 8
            for (int k = 0; k < 256; k++) s = fmaf(bv[k], Wo[k * 256 + t], s);
            g_tmp[t] = s;
        }
        __syncthreads();
#pragma unroll
        for (int l = 0; l < 2; l++) {   // g_bof
            int j = t + l * 256;
            float s = bfp[j];
#pragma unroll 8
            for (int m = 0; m < 256; m++) s = fmaf(g_tmp[m], Wfp[m * 512 + j], s);
            g_bof[j] = s;
        }
        return;
    }
    // ---- Wof tile (64 x 128, K=256) ----
    int bid = blockIdx.x - 1;
    int tx = t & 31, ty = t >> 5;
    int it = bid >> 2, jt = bid & 3;
    float acc[8][4];
#pragma unroll
    for (int i = 0; i < 8; i++)
#pragma unroll
        for (int c = 0; c < 4; c++) acc[i][c] = 0.f;

    for (int mc = 0; mc < 256; mc += 64) {
        __syncthreads();
#pragma unroll
        for (int l = 0; l < 16; l++) {
            int idx = t + l * 256;
            int r = idx >> 6, k = idx & 63;
            sA[r * 65 + k] = Wo[(it * 64 + r) * 256 + mc + k];
        }
        __syncthreads();
#pragma unroll 2
        for (int k = 0; k < 64; k++) {
            const float* Wp = Wfp + (size_t)(mc + k) * 512 + jt * 128 + tx;
            float w[4];
#pragma unroll
            for (int c = 0; c < 4; c++) w[c] = Wp[c * 32];
#pragma unroll
            for (int i = 0; i < 8; i++) {
                float a = sA[(ty * 8 + i) * 65 + k];
#pragma unroll
                for (int c = 0; c < 4; c++) acc[i][c] = fmaf(a, w[c], acc[i][c]);
            }
        }
    }
    __syncthreads();
#pragma unroll
    for (int i = 0; i < 8; i++)
#pragma unroll
        for (int c = 0; c < 4; c++)
            g_Wof[(size_t)(it * 64 + ty * 8 + i) * 512 + jt * 128 + tx + 32 * c] =
                acc[i][c];
}

// ---------------------------- setup kernel 2 --------------------------------
// grid 25 x 256. Blocks 0..23: W5c tiles (3 branches x 4 it x 2 jt, 64x128,
// K=512). Block 24: b5c.
__global__ void setup_fuse(const float* __restrict__ Wip, const float* __restrict__ Wtp,
                           const float* __restrict__ Wc1, const float* __restrict__ bip,
                           const float* __restrict__ btp, const float* __restrict__ bc1) {
    __shared__ float sA[64 * 65];
    int t = threadIdx.x;
    if (blockIdx.x == 24) {
#pragma unroll
        for (int b = 0; b < 3; b++) {
            const float* b5 = (b == 0) ? g_bof : (b == 1) ? bip : btp;
            float s = bc1[t];
#pragma unroll 8
            for (int m = 0; m < 512; m++) s = fmaf(b5[m], Wc1[m * 256 + t], s);
            g_b5c[b * 256 + t] = s;
        }
        return;
    }
    int b = blockIdx.x >> 3, bid = blockIdx.x & 7;
    int it = bid >> 1, jt = bid & 1;  // 4 row tiles x 2 col tiles
    const float* A = (b == 0) ? g_Wof : (b == 1) ? Wip : Wtp;  // [256][512]
    int tx = t & 31, ty = t >> 5;
    float acc[8][4];
#pragma unroll
    for (int i = 0; i < 8; i++)
#pragma unroll
        for (int c = 0; c < 4; c++) acc[i][c] = 0.f;

    for (int mc = 0; mc < 512; mc += 64) {
        __syncthreads();
#pragma unroll
        for (int l = 0; l < 16; l++) {
            int idx = t + l * 256;
            int r = idx >> 6, k = idx & 63;
            sA[r * 65 + k] = A[(size_t)(it * 64 + r) * 512 + mc + k];
        }
        __syncthreads();
#pragma unroll 2
        for (int m = 0; m < 64; m++) {
            const float* Wp = Wc1 + (size_t)(mc + m) * 256 + jt * 128 + tx;
            float w[4];
#pragma unroll
            for (int c = 0; c < 4; c++) w[c] = Wp[c * 32];
#pragma unroll
            for (int i = 0; i < 8; i++) {
                float a = sA[(ty * 8 + i) * 65 + m];
#pragma unroll
                for (int c = 0; c < 4; c++) acc[i][c] = fmaf(a, w[c], acc[i][c]);
            }
        }
    }
    __syncthreads();
#pragma unroll
    for (int i = 0; i < 8; i++)
#pragma unroll
        for (int c = 0; c < 4; c++)
            g_W5c[(size_t)b * 65536 + (size_t)(it * 64 + ty * 8 + i) * 256 +
                  jt * 128 + tx + 32 * c] = acc[i][c];
}

// ------------------------------- main kernel -------------------------------
// 32 rows/CTA (sorted slots), 256 threads (8 warps), 2 CTAs/SM.
// warp w: rg = w&3 (slots rg*8..+7 as 4 row-pairs), nh = w>>2 (N half).
// smem: e0T@0 [256][34], e1T@8704, pT@17408, sAT@26112 [64][34],
//       attn@28288, flag@28416, perm@28448, sbr@28480.
// overlay: h1T @ 0 [256][34] (over e0T, written after all e0T reads).

#define S34 34
#define OFF_E1   8704
#define OFF_PT   17408
#define OFF_SAT  26112
#define OFF_ATTN 28288
#define OFF_FLAG 28416
#define OFF_PERM 28448
#define OFF_SBR  28480
#define SMEM_FLOATS 28512
#define SMEM_BYTES (SMEM_FLOATS * 4)

// Folded projection+classifier1 GEMM: K=256, N=256 (this thread: 4 cols).
template <bool MASKED>
__device__ __forceinline__ void gemm_seg256(u64 (&facc)[4][4],
                                            const float* __restrict__ AT,
                                            const float* __restrict__ W,
                                            const u64* mp, int rg, int nh, int tx) {
    const float* Wb = W + nh * 128 + tx * 4;
    const float* Ab = AT + rg * 8;
#pragma unroll 2
    for (int k = 0; k < 256; k++) {
        float4 w = *(const float4*)(Wb + (size_t)k * 256);
        u64 w0 = pk2(w.x, w.x), w1 = pk2(w.y, w.y);
        u64 w2 = pk2(w.z, w.z), w3 = pk2(w.w, w.w);
        const float* ab = Ab + k * S34;
#pragma unroll
        for (int p = 0; p < 4; p++) {
            u64 ap = *(const u64*)(ab + 2 * p);
            if (MASKED) ap = mul2(ap, mp[p]);
            fma2(facc[p][0], ap, w0);
            fma2(facc[p][1], ap, w1);
            fma2(facc[p][2], ap, w2);
            fma2(facc[p][3], ap, w3);
        }
    }
}

__global__ void __launch_bounds__(256, 2)
fused_main(const float* __restrict__ img, const float* __restrict__ txt,
           const float* __restrict__ W_ie, const float* __restrict__ b_ie,
           const float* __restrict__ W_te, const float* __restrict__ b_te,
           const float* __restrict__ Wv,   const float* __restrict__ bc1,
           const float* __restrict__ Wc2,  const float* __restrict__ bc2,
           float* __restrict__ out) {
    extern __shared__ float sm[];
    float* e0T   = sm;
    float* e1T   = sm + OFF_E1;
    float* pT    = sm + OFF_PT;
    float* sAT   = sm + OFF_SAT;
    float* sattn = sm + OFF_ATTN;
    int*   sflag = (int*)(sm + OFF_FLAG);
    int*   sperm = (int*)(sm + OFF_PERM);
    int*   ssbr  = (int*)(sm + OFF_SBR);
    float* h1T   = sm;  // overlay e0T

    const int tid = threadIdx.x;
    const int tx = tid & 31;
    const int wp = tid >> 5;
    const int rg = wp & 3;
    const int nh = wp >> 2;
    const size_t row0 = (size_t)blockIdx.x * 32;

    // ---------------- P0: presence flags + branch counting sort ------------
    {
        float* npart = sAT;  // [2][32][8]
#pragma unroll
        for (int l = 0; l < 2; l++) {
            int task = tid + l * 256;
            int mod = task >> 8, r = (task >> 3) & 31, p = task & 7;
            const float* X = mod ? txt : img;
            const float4* xp = (const float4*)(X + (row0 + r) * 512 + p * 64);
            float s = 0.f;
#pragma unroll
            for (int u = 0; u < 16; u++) {
                float4 v = xp[u];
                s += v.x * v.x + v.y * v.y + v.z * v.z + v.w * v.w;
            }
            npart[task] = s;
        }
        __syncthreads();
        if (tid < 32) {
            float si = 0.f, st = 0.f;
#pragma unroll
            for (int p = 0; p < 8; p++) {
                si += npart[tid * 8 + p];
                st += npart[256 + tid * 8 + p];
            }
            int fi = si > 1e-12f, ft = st > 1e-12f;  // norm > 1e-6
            sflag[tid] = (fi && ft) ? 1 : (fi ? 2 : (ft ? 3 : 0));
        }
        __syncthreads();
        if (tid == 0) {  // counting sort: both(1), img(2), txt(3), none(0)
            int cnt[4] = {0, 0, 0, 0};
            for (int r = 0; r < 32; r++) cnt[sflag[r]]++;
            int base[4];
            base[1] = 0;
            base[2] = cnt[1];
            base[3] = cnt[1] + cnt[2];
            base[0] = cnt[1] + cnt[2] + cnt[3];
            for (int r = 0; r < 32; r++) {
                int f = sflag[r];
                int s = base[f]++;
                sperm[s] = r;
                ssbr[s]  = f;
            }
        }
        __syncthreads();
    }

    const int b0 = ssbr[rg * 8], bl = ssbr[rg * 8 + 7];
    // Which encoders does this warp's row-group actually need downstream?
    const bool rune0 = (b0 == 1) || (b0 == 2);               // both/img present
    const bool rune1 = (b0 != 0) && !(b0 == 2 && bl == 2);   // not pure-img/none

    // ---------------- P1: encoders (transposed, sorted) --------------------
    for (int mod = 0; mod < 2; mod++) {
        const float* X  = mod ? txt  : img;
        const float* W  = mod ? W_te : W_ie;
        const float* bb = mod ? b_te : b_ie;
        float* eT = mod ? e1T : e0T;
        const bool runm = mod ? rune1 : rune0;

        u64 acc[4][4];
#pragma unroll
        for (int p = 0; p < 4; p++)
#pragma unroll
            for (int c = 0; c < 4; c++) acc[p][c] = 0ULL;

        const float* Wb = W + nh * 128 + tx * 4;
        for (int kc = 0; kc < 512; kc += 64) {
            __syncthreads();
#pragma unroll
            for (int l = 0; l < 2; l++) {
                int idx = tid + l * 256;           // 512 float4 slots
                int s = idx >> 4, k4 = idx & 15;
                float4 v = *(const float4*)(X + (row0 + sperm[s]) * 512 + kc + k4 * 4);
                float* d = sAT + (k4 * 4) * S34 + s;
                d[0] = v.x; d[S34] = v.y; d[2 * S34] = v.z; d[3 * S34] = v.w;
            }
            __syncthreads();
            if (runm) {
#pragma unroll 4
                for (int k = 0; k < 64; k++) {
                    float4 w = *(const float4*)(Wb + (size_t)(kc + k) * 256);
                    u64 w0 = pk2(w.x, w.x), w1 = pk2(w.y, w.y);
                    u64 w2 = pk2(w.z, w.z), w3 = pk2(w.w, w.w);
                    const float* ab = sAT + k * S34 + rg * 8;
#pragma unroll
                    for (int p = 0; p < 4; p++) {
                        u64 ap = *(const u64*)(ab + 2 * p);
                        fma2(acc[p][0], ap, w0);
                        fma2(acc[p][1], ap, w1);
                        fma2(acc[p][2], ap, w2);
                        fma2(acc[p][3], ap, w3);
                    }
                }
            }
        }
        if (runm) {
#pragma unroll
            for (int p = 0; p < 4; p++)
#pragma unroll
                for (int c = 0; c < 4; c++) {
                    int j = nh * 128 + tx * 4 + c;
                    float b = bb[j];
                    float2 v = up2(acc[p][c]);
                    float r0 = v.x + b, r1 = v.y + b;
                    r0 = r0 > 0.f ? r0 : 0.f;
                    r1 = r1 > 0.f ? r1 : 0.f;
                    *(float2*)(eT + j * S34 + rg * 8 + 2 * p) = make_float2(r0, r1);
                }
        }
    }
    __syncthreads();

    // ---------------- P2: folded attention scores + softmax ----------------
    if (tid < 128) {
        int s = tid >> 2, h = tid & 3;
        float di = 0.f, dt = 0.f;
        const float* wkp = g_wk + h * 256;
#pragma unroll 4
        for (int j = 0; j < 256; j++) {
            float w = wkp[j];
            di = fmaf(e0T[j * S34 + s], w, di);
            dt = fmaf(e1T[j * S34 + s], w, dt);
        }
        float s0 = (di + g_ck[h]) * 0.125f;
        float s1 = (dt + g_ck[h]) * 0.125f;
        float m  = fmaxf(s0, s1);
        float e0 = expf(s0 - m), e1 = expf(s1 - m);
        sattn[s * 4 + h] = e0 / (e0 + e1);  // weight on image slot
    }
    __syncthreads();

    // ---------------- P3: pooled = lerp(e1@Wv, e0@Wv, a0), both-warps only -
    if (b0 == 1) {
        u64 q0[4][4], q1[4][4];
#pragma unroll
        for (int p = 0; p < 4; p++)
#pragma unroll
            for (int c = 0; c < 4; c++) { q0[p][c] = 0ULL; q1[p][c] = 0ULL; }

        const float* Wb = Wv + nh * 128 + tx * 4;
#pragma unroll 2
        for (int k = 0; k < 256; k++) {
            float4 w = *(const float4*)(Wb + (size_t)k * 256);
            u64 w0 = pk2(w.x, w.x), w1 = pk2(w.y, w.y);
            u64 w2 = pk2(w.z, w.z), w3 = pk2(w.w, w.w);
            const float* a0b = e0T + k * S34 + rg * 8;
            const float* a1b = e1T + k * S34 + rg * 8;
#pragma unroll
            for (int p = 0; p < 4; p++) {
                u64 ap0 = *(const u64*)(a0b + 2 * p);
                u64 ap1 = *(const u64*)(a1b + 2 * p);
                fma2(q0[p][0], ap0, w0); fma2(q1[p][0], ap1, w0);
                fma2(q0[p][1], ap0, w1); fma2(q1[p][1], ap1, w1);
                fma2(q0[p][2], ap0, w2); fma2(q1[p][2], ap1, w2);
                fma2(q0[p][3], ap0, w3); fma2(q1[p][3], ap1, w3);
            }
        }
#pragma unroll
        for (int p = 0; p < 4; p++) {
            int s0 = rg * 8 + 2 * p;
#pragma unroll
            for (int c = 0; c < 4; c++) {
                int j = nh * 128 + tx * 4 + c;
                int h = j >> 6;
                float a00 = sattn[s0 * 4 + h], a01 = sattn[(s0 + 1) * 4 + h];
                float2 v0 = up2(q0[p][c]), v1 = up2(q1[p][c]);
                float r0 = fmaf(a00, v0.x - v1.x, v1.x);
                float r1 = fmaf(a01, v0.y - v1.y, v1.y);
                *(float2*)(pT + j * S34 + s0) = make_float2(r0, r1);
            }
        }
    }
    __syncthreads();

    // ---------------- P5': folded projection + classifier1 (K=256,N=256) ---
    {
        u64 facc[4][4];
#pragma unroll
        for (int p = 0; p < 4; p++)
#pragma unroll
            for (int c = 0; c < 4; c++) facc[p][c] = 0ULL;

        int br[8];
#pragma unroll
        for (int i = 0; i < 8; i++) br[i] = ssbr[rg * 8 + i];

        if (br[0] == br[7]) {
            if (br[0] == 1)
                gemm_seg256<false>(facc, pT, g_W5c, 0, rg, nh, tx);
            else if (br[0] == 2)
                gemm_seg256<false>(facc, e0T, g_W5c + 65536, 0, rg, nh, tx);
            else if (br[0] == 3)
                gemm_seg256<false>(facc, e1T, g_W5c + 131072, 0, rg, nh, tx);
        } else {
            unsigned need = 0;
#pragma unroll
            for (int i = 0; i < 8; i++) need |= 1u << br[i];
            for (int seg = 1; seg <= 3; seg++) {
                if (!(need & (1u << seg))) continue;
                u64 mp[4];
#pragma unroll
                for (int p = 0; p < 4; p++)
                    mp[p] = pk2(br[2 * p] == seg ? 1.f : 0.f,
                                br[2 * p + 1] == seg ? 1.f : 0.f);
                const float* A = (seg == 1) ? pT : (seg == 2) ? e0T : e1T;
                const float* W = g_W5c + (size_t)(seg - 1) * 65536;
                gemm_seg256<true>(facc, A, W, mp, rg, nh, tx);
            }
        }
        __syncthreads();  // all e0T/e1T/pT reads done before h1T overlay write
#pragma unroll
        for (int p = 0; p < 4; p++) {
            int s0 = rg * 8 + 2 * p;
            int f0 = ssbr[s0], f1 = ssbr[s0 + 1];
            const float* bp0 = (f0 == 0) ? bc1 : g_b5c + (f0 - 1) * 256;
            const float* bp1 = (f1 == 0) ? bc1 : g_b5c + (f1 - 1) * 256;
#pragma unroll
            for (int c = 0; c < 4; c++) {
                int j = nh * 128 + tx * 4 + c;
                float2 v = up2(facc[p][c]);
                float r0 = v.x + bp0[j], r1 = v.y + bp1[j];
                r0 = r0 > 0.f ? r0 : 0.f;
                r1 = r1 > 0.f ? r1 : 0.f;
                *(float2*)(h1T + j * S34 + s0) = make_float2(r0, r1);
            }
        }
        __syncthreads();
    }

    // ---------------- P7: classifier layer 2 (256 -> 80) -------------------
    if (nh == 0) {
        u64 lacc[4][2];
#pragma unroll
        for (int p = 0; p < 4; p++) { lacc[p][0] = 0ULL; lacc[p][1] = 0ULL; }
#pragma unroll 2
        for (int k = 0; k < 256; k++) {
            float2 w = *(const float2*)(Wc2 + (size_t)k * 80 + tx * 2);
            u64 w0 = pk2(w.x, w.x), w1 = pk2(w.y, w.y);
            const float* ab = h1T + k * S34 + rg * 8;
#pragma unroll
            for (int p = 0; p < 4; p++) {
                u64 ap = *(const u64*)(ab + 2 * p);
                fma2(lacc[p][0], ap, w0);
                fma2(lacc[p][1], ap, w1);
            }
        }
#pragma unroll
        for (int p = 0; p < 4; p++) {
            int s0 = rg * 8 + 2 * p;
            size_t r0o = (row0 + sperm[s0]) * 80;
            size_t r1o = (row0 + sperm[s0 + 1]) * 80;
#pragma unroll
            for (int c = 0; c < 2; c++) {
                int j = tx * 2 + c;
                float2 v = up2(lacc[p][c]);
                out[r0o + j] = v.x + bc2[j];
                out[r1o + j] = v.y + bc2[j];
            }
        }
    } else {
        u64 lacc[4];
#pragma unroll
        for (int p = 0; p < 4; p++) lacc[p] = 0ULL;
#pragma unroll 2
        for (int k = 0; k < 256; k++) {
            float w = (tx < 16) ? Wc2[(size_t)k * 80 + 64 + tx] : 0.f;
            u64 w0 = pk2(w, w);
            const float* ab = h1T + k * S34 + rg * 8;
#pragma unroll
            for (int p = 0; p < 4; p++) {
                u64 ap = *(const u64*)(ab + 2 * p);
                fma2(lacc[p], ap, w0);
            }
        }
        if (tx < 16) {
            int j = 64 + tx;
#pragma unroll
            for (int p = 0; p < 4; p++) {
                int s0 = rg * 8 + 2 * p;
                float2 v = up2(lacc[p]);
                out[(row0 + sperm[s0]) * 80 + j]     = v.x + bc2[j];
                out[(row0 + sperm[s0 + 1]) * 80 + j] = v.y + bc2[j];
            }
        }
    }
}

// ------------------------------- launch ------------------------------------

extern "C" void kernel_launch(void* const* d_in, const int* in_sizes, int n_in,
                              void* d_out, int out_size) {
    const float* img  = (const float*)d_in[0];
    const float* txt  = (const float*)d_in[1];
    const float* W_ie = (const float*)d_in[2];
    const float* b_ie = (const float*)d_in[3];
    const float* W_te = (const float*)d_in[4];
    const float* b_te = (const float*)d_in[5];
    const float* fq   = (const float*)d_in[6];
    const float* Wq   = (const float*)d_in[7];
    const float* bq   = (const float*)d_in[8];
    const float* Wk   = (const float*)d_in[9];
    const float* bk   = (const float*)d_in[10];
    const float* Wv   = (const float*)d_in[11];
    const float* bv   = (const float*)d_in[12];
    const float* Wo   = (const float*)d_in[13];
    const float* bo   = (const float*)d_in[14];
    const float* W_ip = (const float*)d_in[15];
    const float* b_ip = (const float*)d_in[16];
    const float* W_tp = (const float*)d_in[17];
    const float* b_tp = (const float*)d_in[18];
    const float* W_fp = (const float*)d_in[19];
    const float* b_fp = (const float*)d_in[20];
    const float* Wc1  = (const float*)d_in[21];
    const float* bc1  = (const float*)d_in[22];
    const float* Wc2  = (const float*)d_in[23];
    const float* bc2  = (const float*)d_in[24];
    float* out = (float*)d_out;

    const int B = in_sizes[0] / 512;

    setup_all<<<17, 256>>>(fq, Wq, bq, Wk, bk, bv, Wo, bo, W_fp, b_fp);
    setup_fuse<<<25, 256>>>(W_ip, W_tp, Wc1, b_ip, b_tp, bc1);

    cudaFuncSetAttribute(fused_main, cudaFuncAttributeMaxDynamicSharedMemorySize,
                         SMEM_BYTES);
    fused_main<<<B / 32, 256, SMEM_BYTES>>>(
        img, txt, W_ie, b_ie, W_te, b_te, Wv, bc1, Wc2, bc2, out);
}

// round 11
// speedup vs baseline: 1.4652x; 1.1047x over previous
#include <cuda_runtime.h>
#include <cuda_bf16.h>
#include <math.h>

typedef unsigned long long u64;
typedef unsigned int u32;
typedef unsigned short u16;
typedef __nv_bfloat16 bf16;
#define BMAX 131072

__device__ __forceinline__ u64 pk2(float x, float y) {
    u64 r; asm("mov.b64 %0,{%1,%2};" : "=l"(r) : "f"(x), "f"(y)); return r;
}
__device__ __forceinline__ void fma2(u64& d, u64 a, u64 b) {
    asm("fma.rn.f32x2 %0,%1,%2,%0;" : "+l"(d) : "l"(a), "l"(b));
}
__device__ __forceinline__ u64 mul2(u64 a, u64 b) {
    u64 r; asm("mul.rn.f32x2 %0,%1,%2;" : "=l"(r) : "l"(a), "l"(b)); return r;
}
__device__ __forceinline__ float2 up2(u64 d) {
    float2 r; asm("mov.b64 {%0,%1},%2;" : "=f"(r.x), "=f"(r.y) : "l"(d)); return r;
}
// m16n8k16 bf16 MMA, f32 accum (sm_80+ PTX, no arch-specific features)
#define MMA16816(c, a, b0_, b1_)                                              \
    asm volatile("mma.sync.aligned.m16n8k16.row.col.f32.bf16.bf16.f32 "       \
                 "{%0,%1,%2,%3},{%4,%5,%6,%7},{%8,%9},{%0,%1,%2,%3};"         \
                 : "+f"((c)[0]), "+f"((c)[1]), "+f"((c)[2]), "+f"((c)[3])     \
                 : "r"((a)[0]), "r"((a)[1]), "r"((a)[2]), "r"((a)[3]),        \
                   "r"(b0_), "r"(b1_))

__device__ __forceinline__ void splitf(float x, u16& h, u16& l) {
    bf16 hb = __float2bfloat16_rn(x);
    bf16 lb = __float2bfloat16_rn(x - __bfloat162float(hb));
    h = *(u16*)&hb; l = *(u16*)&lb;
}

// ------------------------------ device globals ------------------------------
__device__ float g_q[256];
__device__ float g_wk[4 * 256];
__device__ float g_ck[4];
__device__ float g_tmp[256];
__device__ float g_Wof[256 * 512];
__device__ float g_bof[512];
__device__ float g_W5c[3 * 256 * 256];
__device__ float g_b5c[3 * 256];
__device__ float g_e0[(size_t)BMAX * 256];
__device__ float g_e1[(size_t)BMAX * 256];
__device__ u16   g_Wmh[2 * 256 * 512];  // encoder weights [mod][n][k], bf16 hi
__device__ u16   g_Wml[2 * 256 * 512];  // lo

// ---------------------------- setup kernel 1 --------------------------------
__global__ void setup_all(const float* __restrict__ fq, const float* __restrict__ Wq,
                          const float* __restrict__ bq, const float* __restrict__ Wk,
                          const float* __restrict__ bk, const float* __restrict__ bv,
                          const float* __restrict__ Wo, const float* __restrict__ bo,
                          const float* __restrict__ Wfp, const float* __restrict__ bfp) {
    __shared__ float sA[64 * 65];
    int t = threadIdx.x;
    if (blockIdx.x == 0) {
        {
            float s = bq[t];
#pragma unroll 8
            for (int k = 0; k < 256; k++) s = fmaf(fq[k], Wq[k * 256 + t], s);
            g_q[t] = s;
        }
        __syncthreads();
#pragma unroll
        for (int l = 0; l < 4; l++) {
            int idx = t + l * 256;
            int h = idx >> 8, j = idx & 255;
            float s = 0.f;
#pragma unroll 8
            for (int d = 0; d < 64; d++)
                s = fmaf(Wk[j * 256 + h * 64 + d], g_q[h * 64 + d], s);
            g_wk[h * 256 + j] = s;
        }
        if (t < 4) {
            float c = 0.f;
#pragma unroll 8
            for (int d = 0; d < 64; d++) c = fmaf(bk[t * 64 + d], g_q[t * 64 + d], c);
            g_ck[t] = c;
        }
        __syncthreads();
        {
            float s = bo[t];
#pragma unroll 8
            for (int k = 0; k < 256; k++) s = fmaf(bv[k], Wo[k * 256 + t], s);
            g_tmp[t] = s;
        }
        __syncthreads();
#pragma unroll
        for (int l = 0; l < 2; l++) {
            int j = t + l * 256;
            float s = bfp[j];
#pragma unroll 8
            for (int m = 0; m < 256; m++) s = fmaf(g_tmp[m], Wfp[m * 512 + j], s);
            g_bof[j] = s;
        }
        return;
    }
    int bid = blockIdx.x - 1;
    int tx = t & 31, ty = t >> 5;
    int it = bid >> 2, jt = bid & 3;
    float acc[8][4];
#pragma unroll
    for (int i = 0; i < 8; i++)
#pragma unroll
        for (int c = 0; c < 4; c++) acc[i][c] = 0.f;
    for (int mc = 0; mc < 256; mc += 64) {
        __syncthreads();
#pragma unroll
        for (int l = 0; l < 16; l++) {
            int idx = t + l * 256;
            int r = idx >> 6, k = idx & 63;
            sA[r * 65 + k] = Wo[(it * 64 + r) * 256 + mc + k];
        }
        __syncthreads();
#pragma unroll 2
        for (int k = 0; k < 64; k++) {
            const float* Wp = Wfp + (size_t)(mc + k) * 512 + jt * 128 + tx;
            float w[4];
#pragma unroll
            for (int c = 0; c < 4; c++) w[c] = Wp[c * 32];
#pragma unroll
            for (int i = 0; i < 8; i++) {
                float a = sA[(ty * 8 + i) * 65 + k];
#pragma unroll
                for (int c = 0; c < 4; c++) acc[i][c] = fmaf(a, w[c], acc[i][c]);
            }
        }
    }
    __syncthreads();
#pragma unroll
    for (int i = 0; i < 8; i++)
#pragma unroll
        for (int c = 0; c < 4; c++)
            g_Wof[(size_t)(it * 64 + ty * 8 + i) * 512 + jt * 128 + tx + 32 * c] =
                acc[i][c];
}

// ---------------------------- setup kernel 2 --------------------------------
__global__ void setup_fuse(const float* __restrict__ Wip, const float* __restrict__ Wtp,
                           const float* __restrict__ Wc1, const float* __restrict__ bip,
                           const float* __restrict__ btp, const float* __restrict__ bc1) {
    __shared__ float sA[64 * 65];
    int t = threadIdx.x;
    if (blockIdx.x == 24) {
#pragma unroll
        for (int b = 0; b < 3; b++) {
            const float* b5 = (b == 0) ? g_bof : (b == 1) ? bip : btp;
            float s = bc1[t];
#pragma unroll 8
            for (int m = 0; m < 512; m++) s = fmaf(b5[m], Wc1[m * 256 + t], s);
            g_b5c[b * 256 + t] = s;
        }
        return;
    }
    int b = blockIdx.x >> 3, bid = blockIdx.x & 7;
    int it = bid >> 1, jt = bid & 1;
    const float* A = (b == 0) ? g_Wof : (b == 1) ? Wip : Wtp;
    int tx = t & 31, ty = t >> 5;
    float acc[8][4];
#pragma unroll
    for (int i = 0; i < 8; i++)
#pragma unroll
        for (int c = 0; c < 4; c++) acc[i][c] = 0.f;
    for (int mc = 0; mc < 512; mc += 64) {
        __syncthreads();
#pragma unroll
        for (int l = 0; l < 16; l++) {
            int idx = t + l * 256;
            int r = idx >> 6, k = idx & 63;
            sA[r * 65 + k] = A[(size_t)(it * 64 + r) * 512 + mc + k];
        }
        __syncthreads();
#pragma unroll 2
        for (int m = 0; m < 64; m++) {
            const float* Wp = Wc1 + (size_t)(mc + m) * 256 + jt * 128 + tx;
            float w[4];
#pragma unroll
            for (int c = 0; c < 4; c++) w[c] = Wp[c * 32];
#pragma unroll
            for (int i = 0; i < 8; i++) {
                float a = sA[(ty * 8 + i) * 65 + m];
#pragma unroll
                for (int c = 0; c < 4; c++) acc[i][c] = fmaf(a, w[c], acc[i][c]);
            }
        }
    }
    __syncthreads();
#pragma unroll
    for (int i = 0; i < 8; i++)
#pragma unroll
        for (int c = 0; c < 4; c++)
            g_W5c[(size_t)b * 65536 + (size_t)(it * 64 + ty * 8 + i) * 256 +
                  jt * 128 + tx + 32 * c] = acc[i][c];
}

// -------------------- setup 3: split-convert encoder weights ----------------
__global__ void setup_conv(const float* __restrict__ Wie, const float* __restrict__ Wte) {
    int idx = blockIdx.x * 256 + threadIdx.x;  // 0..262143
    int mod = idx >> 17;
    int loc = idx & 131071;
    int n = loc >> 9, k = loc & 511;
    const float* W = mod ? Wte : Wie;
    float v = W[(size_t)k * 256 + n];
    u16 h, l;
    splitf(v, h, l);
    size_t o = (size_t)mod * 131072 + (size_t)n * 512 + k;
    g_Wmh[o] = h;
    g_Wml[o] = l;
}

// ------------------- encoder kernel (mma.sync HMMA bf16) --------------------
// grid (B/64, 2), 256 threads (8 warps). Warp w: out-cols [w*32, w*32+32),
// all 64 rows. Split-bf16 (3 MMA passes). A = weights (global), B = acts (smem).
#define ENC_STRIDE 264  // u16 per staged row (256 + 8 pad)
#define ENC_SMEM (2 * 64 * ENC_STRIDE * 2)

__global__ void __launch_bounds__(256, 2)
enc_kernel(const float* __restrict__ img, const float* __restrict__ txt,
           const float* __restrict__ b_ie, const float* __restrict__ b_te) {
    extern __shared__ u16 smh[];
    u16* Ah = smh;
    u16* Al = smh + 64 * ENC_STRIDE;
    const int tid = threadIdx.x;
    const int lane = tid & 31, w = tid >> 5;
    const int g = lane >> 2, tig = lane & 3;
    const int mod = blockIdx.y;
    const size_t row0 = (size_t)blockIdx.x * 64;
    const float* X  = mod ? txt : img;
    const float* bb = mod ? b_te : b_ie;
    const u16* Wh = g_Wmh + (size_t)mod * 131072;
    const u16* Wl = g_Wml + (size_t)mod * 131072;
    float* eP = mod ? g_e1 : g_e0;

    float acc[2][8][4] = {};

    for (int kc = 0; kc < 512; kc += 256) {
        __syncthreads();
        // stage acts fp32 -> split bf16 [row][k]
#pragma unroll
        for (int l = 0; l < 16; l++) {
            int idx = tid + l * 256;
            int r = idx >> 6, k4 = idx & 63;
            float4 v = *(const float4*)(X + (row0 + r) * 512 + kc + k4 * 4);
            u16 h[4], lo[4];
            splitf(v.x, h[0], lo[0]); splitf(v.y, h[1], lo[1]);
            splitf(v.z, h[2], lo[2]); splitf(v.w, h[3], lo[3]);
            u32 base = r * ENC_STRIDE + k4 * 4;
            *(u32*)(Ah + base)     = (u32)h[0] | ((u32)h[1] << 16);
            *(u32*)(Ah + base + 2) = (u32)h[2] | ((u32)h[3] << 16);
            *(u32*)(Al + base)     = (u32)lo[0] | ((u32)lo[1] << 16);
            *(u32*)(Al + base + 2) = (u32)lo[2] | ((u32)lo[3] << 16);
        }
        __syncthreads();
#pragma unroll 2
        for (int ks = 0; ks < 16; ks++) {
            int kof = kc + ks * 16;
            u32 ah[2][4], al[2][4];
#pragma unroll
            for (int mt = 0; mt < 2; mt++) {
                int m = w * 32 + mt * 16 + g;
                size_t o0 = (size_t)m * 512 + kof + 2 * tig;
                size_t o8 = o0 + 8 * 512;
                ah[mt][0] = *(const u32*)(Wh + o0);
                ah[mt][1] = *(const u32*)(Wh + o8);
                ah[mt][2] = *(const u32*)(Wh + o0 + 8);
                ah[mt][3] = *(const u32*)(Wh + o8 + 8);
                al[mt][0] = *(const u32*)(Wl + o0);
                al[mt][1] = *(const u32*)(Wl + o8);
                al[mt][2] = *(const u32*)(Wl + o0 + 8);
                al[mt][3] = *(const u32*)(Wl + o8 + 8);
            }
            int ko = ks * 16;
#pragma unroll
            for (int nt = 0; nt < 8; nt++) {
                const u16* ar  = Ah + (nt * 8 + g) * ENC_STRIDE + ko;
                const u16* arl = Al + (nt * 8 + g) * ENC_STRIDE + ko;
                u32 bh0 = *(const u32*)(ar + 2 * tig);
                u32 bh1 = *(const u32*)(ar + 2 * tig + 8);
                u32 bl0 = *(const u32*)(arl + 2 * tig);
                u32 bl1 = *(const u32*)(arl + 2 * tig + 8);
#pragma unroll
                for (int mt = 0; mt < 2; mt++) {
                    MMA16816(acc[mt][nt], ah[mt], bh0, bh1);
                    MMA16816(acc[mt][nt], ah[mt], bl0, bl1);
                    MMA16816(acc[mt][nt], al[mt], bh0, bh1);
                }
            }
        }
    }
    // epilogue: bias + relu -> e plane (C frag: rows=out-cols, cols=batch rows)
#pragma unroll
    for (int mt = 0; mt < 2; mt++) {
        int m0 = w * 32 + mt * 16 + g;
        float b0 = bb[m0], b8 = bb[m0 + 8];
#pragma unroll
        for (int nt = 0; nt < 8; nt++) {
            size_t r0 = row0 + nt * 8 + 2 * tig;
            float v;
            v = acc[mt][nt][0] + b0; eP[r0 * 256 + m0]           = v > 0.f ? v : 0.f;
            v = acc[mt][nt][1] + b0; eP[(r0 + 1) * 256 + m0]     = v > 0.f ? v : 0.f;
            v = acc[mt][nt][2] + b8; eP[r0 * 256 + m0 + 8]       = v > 0.f ? v : 0.f;
            v = acc[mt][nt][3] + b8; eP[(r0 + 1) * 256 + m0 + 8] = v > 0.f ? v : 0.f;
        }
    }
}

// ------------------------------- tail kernel --------------------------------
#define S34 34
#define OFF_E1   8704
#define OFF_PT   17408
#define OFF_ATTN 26112
#define OFF_FLAG 26240
#define OFF_PERM 26272
#define OFF_SBR  26304
#define SMEM_FLOATS 26336
#define SMEM_BYTES (SMEM_FLOATS * 4)

template <bool MASKED>
__device__ __forceinline__ void gemm_seg256(u64 (&facc)[4][4],
                                            const float* __restrict__ AT,
                                            const float* __restrict__ W,
                                            const u64* mp, int rg, int nh, int tx) {
    const float* Wb = W + nh * 128 + tx * 4;
    const float* Ab = AT + rg * 8;
#pragma unroll 2
    for (int k = 0; k < 256; k++) {
        float4 w = *(const float4*)(Wb + (size_t)k * 256);
        u64 w0 = pk2(w.x, w.x), w1 = pk2(w.y, w.y);
        u64 w2 = pk2(w.z, w.z), w3 = pk2(w.w, w.w);
        const float* ab = Ab + k * S34;
#pragma unroll
        for (int p = 0; p < 4; p++) {
            u64 ap = *(const u64*)(ab + 2 * p);
            if (MASKED) ap = mul2(ap, mp[p]);
            fma2(facc[p][0], ap, w0);
            fma2(facc[p][1], ap, w1);
            fma2(facc[p][2], ap, w2);
            fma2(facc[p][3], ap, w3);
        }
    }
}

__global__ void __launch_bounds__(256, 2)
fused_tail(const float* __restrict__ img, const float* __restrict__ txt,
           const float* __restrict__ Wv, const float* __restrict__ bc1,
           const float* __restrict__ Wc2, const float* __restrict__ bc2,
           float* __restrict__ out) {
    extern __shared__ float sm[];
    float* e0T   = sm;
    float* e1T   = sm + OFF_E1;
    float* pT    = sm + OFF_PT;
    float* sattn = sm + OFF_ATTN;
    int*   sflag = (int*)(sm + OFF_FLAG);
    int*   sperm = (int*)(sm + OFF_PERM);
    int*   ssbr  = (int*)(sm + OFF_SBR);
    float* h1T   = sm;  // overlay e0T

    const int tid = threadIdx.x;
    const int tx = tid & 31;
    const int wp = tid >> 5;
    const int rg = wp & 3;
    const int nh = wp >> 2;
    const size_t row0 = (size_t)blockIdx.x * 32;

    // ---- P0: presence flags + branch counting sort (raw inputs, exact) ----
    {
        float* npart = pT;  // scratch [2][32][8]
#pragma unroll
        for (int l = 0; l < 2; l++) {
            int task = tid + l * 256;
            int mod = task >> 8, r = (task >> 3) & 31, p = task & 7;
            const float* X = mod ? txt : img;
            const float4* xp = (const float4*)(X + (row0 + r) * 512 + p * 64);
            float s = 0.f;
#pragma unroll
            for (int u = 0; u < 16; u++) {
                float4 v = xp[u];
                s += v.x * v.x + v.y * v.y + v.z * v.z + v.w * v.w;
            }
            npart[task] = s;
        }
        __syncthreads();
        if (tid < 32) {
            float si = 0.f, st = 0.f;
#pragma unroll
            for (int p = 0; p < 8; p++) {
                si += npart[tid * 8 + p];
                st += npart[256 + tid * 8 + p];
            }
            int fi = si > 1e-12f, ft = st > 1e-12f;
            sflag[tid] = (fi && ft) ? 1 : (fi ? 2 : (ft ? 3 : 0));
        }
        __syncthreads();
        if (tid == 0) {
            int cnt[4] = {0, 0, 0, 0};
            for (int r = 0; r < 32; r++) cnt[sflag[r]]++;
            int base[4];
            base[1] = 0;
            base[2] = cnt[1];
            base[3] = cnt[1] + cnt[2];
            base[0] = cnt[1] + cnt[2] + cnt[3];
            for (int r = 0; r < 32; r++) {
                int f = sflag[r];
                int s = base[f]++;
                sperm[s] = r;
                ssbr[s]  = f;
            }
        }
        __syncthreads();
    }

    // ---- P1': gather e planes (sorted, transposed) ----
#pragma unroll
    for (int l = 0; l < 16; l++) {
        int task = tid + l * 256;
        int md = task >> 11;
        int s = (task >> 6) & 31;
        int j4 = task & 63;
        const float* src = (md ? g_e1 : g_e0) + (row0 + sperm[s]) * 256 + j4 * 4;
        float4 v = *(const float4*)src;
        float* d = (md ? e1T : e0T) + (j4 * 4) * S34 + s;
        d[0] = v.x; d[S34] = v.y; d[2 * S34] = v.z; d[3 * S34] = v.w;
    }
    __syncthreads();

    // ---- P2: folded attention scores + softmax ----
    if (tid < 128) {
        int s = tid >> 2, h = tid & 3;
        float di = 0.f, dt = 0.f;
        const float* wkp = g_wk + h * 256;
#pragma unroll 4
        for (int j = 0; j < 256; j++) {
            float w = wkp[j];
            di = fmaf(e0T[j * S34 + s], w, di);
            dt = fmaf(e1T[j * S34 + s], w, dt);
        }
        float s0 = (di + g_ck[h]) * 0.125f;
        float s1 = (dt + g_ck[h]) * 0.125f;
        float m = fmaxf(s0, s1);
        float e0 = expf(s0 - m), e1 = expf(s1 - m);
        sattn[s * 4 + h] = e0 / (e0 + e1);
    }
    __syncthreads();

    const int b0 = ssbr[rg * 8];

    // ---- P3: pooled = lerp(e1@Wv, e0@Wv, a0), both-warps only ----
    if (b0 == 1) {
        u64 q0[4][4], q1[4][4];
#pragma unroll
        for (int p = 0; p < 4; p++)
#pragma unroll
            for (int c = 0; c < 4; c++) { q0[p][c] = 0ULL; q1[p][c] = 0ULL; }
        const float* Wb = Wv + nh * 128 + tx * 4;
#pragma unroll 2
        for (int k = 0; k < 256; k++) {
            float4 w = *(const float4*)(Wb + (size_t)k * 256);
            u64 w0 = pk2(w.x, w.x), w1 = pk2(w.y, w.y);
            u64 w2 = pk2(w.z, w.z), w3 = pk2(w.w, w.w);
            const float* a0b = e0T + k * S34 + rg * 8;
            const float* a1b = e1T + k * S34 + rg * 8;
#pragma unroll
            for (int p = 0; p < 4; p++) {
                u64 ap0 = *(const u64*)(a0b + 2 * p);
                u64 ap1 = *(const u64*)(a1b + 2 * p);
                fma2(q0[p][0], ap0, w0); fma2(q1[p][0], ap1, w0);
                fma2(q0[p][1], ap0, w1); fma2(q1[p][1], ap1, w1);
                fma2(q0[p][2], ap0, w2); fma2(q1[p][2], ap1, w2);
                fma2(q0[p][3], ap0, w3); fma2(q1[p][3], ap1, w3);
            }
        }
#pragma unroll
        for (int p = 0; p < 4; p++) {
            int s0 = rg * 8 + 2 * p;
#pragma unroll
            for (int c = 0; c < 4; c++) {
                int j = nh * 128 + tx * 4 + c;
                int h = j >> 6;
                float a00 = sattn[s0 * 4 + h], a01 = sattn[(s0 + 1) * 4 + h];
                float2 v0 = up2(q0[p][c]), v1 = up2(q1[p][c]);
                float r0 = fmaf(a00, v0.x - v1.x, v1.x);
                float r1 = fmaf(a01, v0.y - v1.y, v1.y);
                *(float2*)(pT + j * S34 + s0) = make_float2(r0, r1);
            }
        }
    }
    __syncthreads();

    // ---- P5': folded projection + classifier1 ----
    {
        u64 facc[4][4];
#pragma unroll
        for (int p = 0; p < 4; p++)
#pragma unroll
            for (int c = 0; c < 4; c++) facc[p][c] = 0ULL;
        int br[8];
#pragma unroll
        for (int i = 0; i < 8; i++) br[i] = ssbr[rg * 8 + i];
        if (br[0] == br[7]) {
            if (br[0] == 1)
                gemm_seg256<false>(facc, pT, g_W5c, 0, rg, nh, tx);
            else if (br[0] == 2)
                gemm_seg256<false>(facc, e0T, g_W5c + 65536, 0, rg, nh, tx);
            else if (br[0] == 3)
                gemm_seg256<false>(facc, e1T, g_W5c + 131072, 0, rg, nh, tx);
        } else {
            unsigned need = 0;
#pragma unroll
            for (int i = 0; i < 8; i++) need |= 1u << br[i];
            for (int seg = 1; seg <= 3; seg++) {
                if (!(need & (1u << seg))) continue;
                u64 mp[4];
#pragma unroll
                for (int p = 0; p < 4; p++)
                    mp[p] = pk2(br[2 * p] == seg ? 1.f : 0.f,
                                br[2 * p + 1] == seg ? 1.f : 0.f);
                const float* A = (seg == 1) ? pT : (seg == 2) ? e0T : e1T;
                const float* W = g_W5c + (size_t)(seg - 1) * 65536;
                gemm_seg256<true>(facc, A, W, mp, rg, nh, tx);
            }
        }
        __syncthreads();
#pragma unroll
        for (int p = 0; p < 4; p++) {
            int s0 = rg * 8 + 2 * p;
            int f0 = ssbr[s0], f1 = ssbr[s0 + 1];
            const float* bp0 = (f0 == 0) ? bc1 : g_b5c + (f0 - 1) * 256;
            const float* bp1 = (f1 == 0) ? bc1 : g_b5c + (f1 - 1) * 256;
#pragma unroll
            for (int c = 0; c < 4; c++) {
                int j = nh * 128 + tx * 4 + c;
                float2 v = up2(facc[p][c]);
                float r0 = v.x + bp0[j], r1 = v.y + bp1[j];
                r0 = r0 > 0.f ? r0 : 0.f;
                r1 = r1 > 0.f ? r1 : 0.f;
                *(float2*)(h1T + j * S34 + s0) = make_float2(r0, r1);
            }
        }
        __syncthreads();
    }

    // ---- P7: classifier layer 2 (256 -> 80) ----
    if (nh == 0) {
        u64 lacc[4][2];
#pragma unroll
        for (int p = 0; p < 4; p++) { lacc[p][0] = 0ULL; lacc[p][1] = 0ULL; }
#pragma unroll 2
        for (int k = 0; k < 256; k++) {
            float2 w = *(const float2*)(Wc2 + (size_t)k * 80 + tx * 2);
            u64 w0 = pk2(w.x, w.x), w1 = pk2(w.y, w.y);
            const float* ab = h1T + k * S34 + rg * 8;
#pragma unroll
            for (int p = 0; p < 4; p++) {
                u64 ap = *(const u64*)(ab + 2 * p);
                fma2(lacc[p][0], ap, w0);
                fma2(lacc[p][1], ap, w1);
            }
        }
#pragma unroll
        for (int p = 0; p < 4; p++) {
            int s0 = rg * 8 + 2 * p;
            size_t r0o = (row0 + sperm[s0]) * 80;
            size_t r1o = (row0 + sperm[s0 + 1]) * 80;
#pragma unroll
            for (int c = 0; c < 2; c++) {
                int j = tx * 2 + c;
                float2 v = up2(lacc[p][c]);
                out[r0o + j] = v.x + bc2[j];
                out[r1o + j] = v.y + bc2[j];
            }
        }
    } else {
        u64 lacc[4];
#pragma unroll
        for (int p = 0; p < 4; p++) lacc[p] = 0ULL;
#pragma unroll 2
        for (int k = 0; k < 256; k++) {
            float w = (tx < 16) ? Wc2[(size_t)k * 80 + 64 + tx] : 0.f;
            u64 w0 = pk2(w, w);
            const float* ab = h1T + k * S34 + rg * 8;
#pragma unroll
            for (int p = 0; p < 4; p++) {
                u64 ap = *(const u64*)(ab + 2 * p);
                fma2(lacc[p], ap, w0);
            }
        }
        if (tx < 16) {
            int j = 64 + tx;
#pragma unroll
            for (int p = 0; p < 4; p++) {
                int s0 = rg * 8 + 2 * p;
                float2 v = up2(lacc[p]);
                out[(row0 + sperm[s0]) * 80 + j]     = v.x + bc2[j];
                out[(row0 + sperm[s0 + 1]) * 80 + j] = v.y + bc2[j];
            }
        }
    }
}

// ------------------------------- launch ------------------------------------
extern "C" void kernel_launch(void* const* d_in, const int* in_sizes, int n_in,
                              void* d_out, int out_size) {
    const float* img  = (const float*)d_in[0];
    const float* txt  = (const float*)d_in[1];
    const float* W_ie = (const float*)d_in[2];
    const float* b_ie = (const float*)d_in[3];
    const float* W_te = (const float*)d_in[4];
    const float* b_te = (const float*)d_in[5];
    const float* fq   = (const float*)d_in[6];
    const float* Wq   = (const float*)d_in[7];
    const float* bq   = (const float*)d_in[8];
    const float* Wk   = (const float*)d_in[9];
    const float* bk   = (const float*)d_in[10];
    const float* Wv   = (const float*)d_in[11];
    const float* bv   = (const float*)d_in[12];
    const float* Wo   = (const float*)d_in[13];
    const float* bo   = (const float*)d_in[14];
    const float* W_ip = (const float*)d_in[15];
    const float* b_ip = (const float*)d_in[16];
    const float* W_tp = (const float*)d_in[17];
    const float* b_tp = (const float*)d_in[18];
    const float* W_fp = (const float*)d_in[19];
    const float* b_fp = (const float*)d_in[20];
    const float* Wc1  = (const float*)d_in[21];
    const float* bc1  = (const float*)d_in[22];
    const float* Wc2  = (const float*)d_in[23];
    const float* bc2  = (const float*)d_in[24];
    float* out = (float*)d_out;

    const int B = in_sizes[0] / 512;

    setup_all<<<17, 256>>>(fq, Wq, bq, Wk, bk, bv, Wo, bo, W_fp, b_fp);
    setup_fuse<<<25, 256>>>(W_ip, W_tp, Wc1, b_ip, b_tp, bc1);
    setup_conv<<<1024, 256>>>(W_ie, W_te);

    cudaFuncSetAttribute(enc_kernel, cudaFuncAttributeMaxDynamicSharedMemorySize,
                         ENC_SMEM);
    enc_kernel<<<dim3(B / 64, 2), 256, ENC_SMEM>>>(img, txt, b_ie, b_te);

    cudaFuncSetAttribute(fused_tail, cudaFuncAttributeMaxDynamicSharedMemorySize,
                         SMEM_BYTES);
    fused_tail<<<B / 32, 256, SMEM_BYTES>>>(img, txt, Wv, bc1, Wc2, bc2, out);
}

// round 12
// speedup vs baseline: 1.7918x; 1.2229x over previous
#include <cuda_runtime.h>
#include <cuda_bf16.h>
#include <math.h>

typedef unsigned long long u64;
typedef unsigned int u32;
typedef unsigned short u16;
typedef __nv_bfloat16 bf16;
#define BMAX 131072

#define MMA16816(c, a, b0_, b1_)                                              \
    asm volatile("mma.sync.aligned.m16n8k16.row.col.f32.bf16.bf16.f32 "       \
                 "{%0,%1,%2,%3},{%4,%5,%6,%7},{%8,%9},{%0,%1,%2,%3};"         \
                 : "+f"((c)[0]), "+f"((c)[1]), "+f"((c)[2]), "+f"((c)[3])     \
                 : "r"((a)[0]), "r"((a)[1]), "r"((a)[2]), "r"((a)[3]),        \
                   "r"(b0_), "r"(b1_))

__device__ __forceinline__ void splitf(float x, u16& h, u16& l) {
    bf16 hb = __float2bfloat16_rn(x);
    bf16 lb = __float2bfloat16_rn(x - __bfloat162float(hb));
    h = *(u16*)&hb; l = *(u16*)&lb;
}
__device__ __forceinline__ float b2f(u32 u) { return __uint_as_float(u << 16); }

// ------------------------------ device globals ------------------------------
__device__ float g_q[256];
__device__ float g_wk[4 * 256];
__device__ float g_ck[4];
__device__ float g_tmp[256];
__device__ float g_Wof[256 * 512];
__device__ float g_bof[512];
__device__ float g_W5c[3 * 256 * 256];   // [b][k][n]
__device__ float g_b5c[3 * 256];
__device__ float g_e0[(size_t)BMAX * 256];
__device__ float g_e1[(size_t)BMAX * 256];
__device__ u16   g_Wmh[2 * 256 * 512], g_Wml[2 * 256 * 512];   // enc W [mod][n][k]
__device__ u16   g_Wvh[256 * 256],     g_Wvl[256 * 256];       // Wv^T  [n][k]
__device__ u16   g_W5h[3 * 256 * 256], g_W5l[3 * 256 * 256];   // W5c^T [b][n][k]
__device__ u16   g_Wch[80 * 256],      g_Wcl[80 * 256];        // Wc2^T [n][k]

// ---------------------------- setup kernel 1 --------------------------------
__global__ void setup_all(const float* __restrict__ fq, const float* __restrict__ Wq,
                          const float* __restrict__ bq, const float* __restrict__ Wk,
                          const float* __restrict__ bk, const float* __restrict__ bv,
                          const float* __restrict__ Wo, const float* __restrict__ bo,
                          const float* __restrict__ Wfp, const float* __restrict__ bfp) {
    __shared__ float sA[64 * 65];
    int t = threadIdx.x;
    if (blockIdx.x == 0) {
        {
            float s = bq[t];
#pragma unroll 8
            for (int k = 0; k < 256; k++) s = fmaf(fq[k], Wq[k * 256 + t], s);
            g_q[t] = s;
        }
        __syncthreads();
#pragma unroll
        for (int l = 0; l < 4; l++) {
            int idx = t + l * 256;
            int h = idx >> 8, j = idx & 255;
            float s = 0.f;
#pragma unroll 8
            for (int d = 0; d < 64; d++)
                s = fmaf(Wk[j * 256 + h * 64 + d], g_q[h * 64 + d], s);
            g_wk[h * 256 + j] = s;
        }
        if (t < 4) {
            float c = 0.f;
#pragma unroll 8
            for (int d = 0; d < 64; d++) c = fmaf(bk[t * 64 + d], g_q[t * 64 + d], c);
            g_ck[t] = c;
        }
        __syncthreads();
        {
            float s = bo[t];
#pragma unroll 8
            for (int k = 0; k < 256; k++) s = fmaf(bv[k], Wo[k * 256 + t], s);
            g_tmp[t] = s;
        }
        __syncthreads();
#pragma unroll
        for (int l = 0; l < 2; l++) {
            int j = t + l * 256;
            float s = bfp[j];
#pragma unroll 8
            for (int m = 0; m < 256; m++) s = fmaf(g_tmp[m], Wfp[m * 512 + j], s);
            g_bof[j] = s;
        }
        return;
    }
    int bid = blockIdx.x - 1;
    int tx = t & 31, ty = t >> 5;
    int it = bid >> 2, jt = bid & 3;
    float acc[8][4];
#pragma unroll
    for (int i = 0; i < 8; i++)
#pragma unroll
        for (int c = 0; c < 4; c++) acc[i][c] = 0.f;
    for (int mc = 0; mc < 256; mc += 64) {
        __syncthreads();
#pragma unroll
        for (int l = 0; l < 16; l++) {
            int idx = t + l * 256;
            int r = idx >> 6, k = idx & 63;
            sA[r * 65 + k] = Wo[(it * 64 + r) * 256 + mc + k];
        }
        __syncthreads();
#pragma unroll 2
        for (int k = 0; k < 64; k++) {
            const float* Wp = Wfp + (size_t)(mc + k) * 512 + jt * 128 + tx;
            float w[4];
#pragma unroll
            for (int c = 0; c < 4; c++) w[c] = Wp[c * 32];
#pragma unroll
            for (int i = 0; i < 8; i++) {
                float a = sA[(ty * 8 + i) * 65 + k];
#pragma unroll
                for (int c = 0; c < 4; c++) acc[i][c] = fmaf(a, w[c], acc[i][c]);
            }
        }
    }
    __syncthreads();
#pragma unroll
    for (int i = 0; i < 8; i++)
#pragma unroll
        for (int c = 0; c < 4; c++)
            g_Wof[(size_t)(it * 64 + ty * 8 + i) * 512 + jt * 128 + tx + 32 * c] =
                acc[i][c];
}

// ---------------------------- setup kernel 2 --------------------------------
__global__ void setup_fuse(const float* __restrict__ Wip, const float* __restrict__ Wtp,
                           const float* __restrict__ Wc1, const float* __restrict__ bip,
                           const float* __restrict__ btp, const float* __restrict__ bc1) {
    __shared__ float sA[64 * 65];
    int t = threadIdx.x;
    if (blockIdx.x == 24) {
#pragma unroll
        for (int b = 0; b < 3; b++) {
            const float* b5 = (b == 0) ? g_bof : (b == 1) ? bip : btp;
            float s = bc1[t];
#pragma unroll 8
            for (int m = 0; m < 512; m++) s = fmaf(b5[m], Wc1[m * 256 + t], s);
            g_b5c[b * 256 + t] = s;
        }
        return;
    }
    int b = blockIdx.x >> 3, bid = blockIdx.x & 7;
    int it = bid >> 1, jt = bid & 1;
    const float* A = (b == 0) ? g_Wof : (b == 1) ? Wip : Wtp;
    int tx = t & 31, ty = t >> 5;
    float acc[8][4];
#pragma unroll
    for (int i = 0; i < 8; i++)
#pragma unroll
        for (int c = 0; c < 4; c++) acc[i][c] = 0.f;
    for (int mc = 0; mc < 512; mc += 64) {
        __syncthreads();
#pragma unroll
        for (int l = 0; l < 16; l++) {
            int idx = t + l * 256;
            int r = idx >> 6, k = idx & 63;
            sA[r * 65 + k] = A[(size_t)(it * 64 + r) * 512 + mc + k];
        }
        __syncthreads();
#pragma unroll 2
        for (int m = 0; m < 64; m++) {
            const float* Wp = Wc1 + (size_t)(mc + m) * 256 + jt * 128 + tx;
            float w[4];
#pragma unroll
            for (int c = 0; c < 4; c++) w[c] = Wp[c * 32];
#pragma unroll
            for (int i = 0; i < 8; i++) {
                float a = sA[(ty * 8 + i) * 65 + m];
#pragma unroll
                for (int c = 0; c < 4; c++) acc[i][c] = fmaf(a, w[c], acc[i][c]);
            }
        }
    }
    __syncthreads();
#pragma unroll
    for (int i = 0; i < 8; i++)
#pragma unroll
        for (int c = 0; c < 4; c++)
            g_W5c[(size_t)b * 65536 + (size_t)(it * 64 + ty * 8 + i) * 256 +
                  jt * 128 + tx + 32 * c] = acc[i][c];
}

// ---------------- setup 3/4: split-convert weights ----------------
__global__ void setup_conv(const float* __restrict__ Wie, const float* __restrict__ Wte) {
    int idx = blockIdx.x * 256 + threadIdx.x;
    int mod = idx >> 17, loc = idx & 131071;
    int n = loc >> 9, k = loc & 511;
    const float* W = mod ? Wte : Wie;
    u16 h, l;
    splitf(W[(size_t)k * 256 + n], h, l);
    size_t o = (size_t)mod * 131072 + (size_t)n * 512 + k;
    g_Wmh[o] = h; g_Wml[o] = l;
}
__global__ void setup_conv2(const float* __restrict__ Wv, const float* __restrict__ Wc2) {
    int idx = blockIdx.x * 256 + threadIdx.x;
    u16 h, l;
    if (idx < 65536) {
        int n = idx >> 8, k = idx & 255;
        splitf(Wv[k * 256 + n], h, l);
        g_Wvh[n * 256 + k] = h; g_Wvl[n * 256 + k] = l;
    } else if (idx < 262144) {
        int t = idx - 65536, b = t >> 16, r = t & 65535;
        int n = r >> 8, k = r & 255;
        splitf(g_W5c[b * 65536 + k * 256 + n], h, l);
        g_W5h[b * 65536 + n * 256 + k] = h; g_W5l[b * 65536 + n * 256 + k] = l;
    } else if (idx < 282624) {
        int t = idx - 262144, n = t >> 8, k = t & 255;
        splitf(Wc2[k * 80 + n], h, l);
        g_Wch[n * 256 + k] = h; g_Wcl[n * 256 + k] = l;
    }
}

// ------------------- encoder kernel (HMMA, unchanged) -----------------------
#define ENC_STRIDE 264
#define ENC_SMEM (2 * 64 * ENC_STRIDE * 2)

__global__ void __launch_bounds__(256, 2)
enc_kernel(const float* __restrict__ img, const float* __restrict__ txt,
           const float* __restrict__ b_ie, const float* __restrict__ b_te) {
    extern __shared__ u16 smh[];
    u16* Ah = smh;
    u16* Al = smh + 64 * ENC_STRIDE;
    const int tid = threadIdx.x;
    const int lane = tid & 31, w = tid >> 5;
    const int g = lane >> 2, tig = lane & 3;
    const int mod = blockIdx.y;
    const size_t row0 = (size_t)blockIdx.x * 64;
    const float* X  = mod ? txt : img;
    const float* bb = mod ? b_te : b_ie;
    const u16* Wh = g_Wmh + (size_t)mod * 131072;
    const u16* Wl = g_Wml + (size_t)mod * 131072;
    float* eP = mod ? g_e1 : g_e0;
    float acc[2][8][4] = {};

    for (int kc = 0; kc < 512; kc += 256) {
        __syncthreads();
#pragma unroll
        for (int l = 0; l < 16; l++) {
            int idx = tid + l * 256;
            int r = idx >> 6, k4 = idx & 63;
            float4 v = *(const float4*)(X + (row0 + r) * 512 + kc + k4 * 4);
            u16 h[4], lo[4];
            splitf(v.x, h[0], lo[0]); splitf(v.y, h[1], lo[1]);
            splitf(v.z, h[2], lo[2]); splitf(v.w, h[3], lo[3]);
            u32 base = r * ENC_STRIDE + k4 * 4;
            *(u32*)(Ah + base)     = (u32)h[0] | ((u32)h[1] << 16);
            *(u32*)(Ah + base + 2) = (u32)h[2] | ((u32)h[3] << 16);
            *(u32*)(Al + base)     = (u32)lo[0] | ((u32)lo[1] << 16);
            *(u32*)(Al + base + 2) = (u32)lo[2] | ((u32)lo[3] << 16);
        }
        __syncthreads();
#pragma unroll 2
        for (int ks = 0; ks < 16; ks++) {
            int kof = kc + ks * 16;
            u32 ah[2][4], al[2][4];
#pragma unroll
            for (int mt = 0; mt < 2; mt++) {
                int m = w * 32 + mt * 16 + g;
                size_t o0 = (size_t)m * 512 + kof + 2 * tig, o8 = o0 + 8 * 512;
                ah[mt][0] = *(const u32*)(Wh + o0); ah[mt][1] = *(const u32*)(Wh + o8);
                ah[mt][2] = *(const u32*)(Wh + o0 + 8); ah[mt][3] = *(const u32*)(Wh + o8 + 8);
                al[mt][0] = *(const u32*)(Wl + o0); al[mt][1] = *(const u32*)(Wl + o8);
                al[mt][2] = *(const u32*)(Wl + o0 + 8); al[mt][3] = *(const u32*)(Wl + o8 + 8);
            }
            int ko = ks * 16;
#pragma unroll
            for (int nt = 0; nt < 8; nt++) {
                const u16* ar  = Ah + (nt * 8 + g) * ENC_STRIDE + ko;
                const u16* arl = Al + (nt * 8 + g) * ENC_STRIDE + ko;
                u32 bh0 = *(const u32*)(ar + 2 * tig);
                u32 bh1 = *(const u32*)(ar + 2 * tig + 8);
                u32 bl0 = *(const u32*)(arl + 2 * tig);
                u32 bl1 = *(const u32*)(arl + 2 * tig + 8);
#pragma unroll
                for (int mt = 0; mt < 2; mt++) {
                    MMA16816(acc[mt][nt], ah[mt], bh0, bh1);
                    MMA16816(acc[mt][nt], ah[mt], bl0, bl1);
                    MMA16816(acc[mt][nt], al[mt], bh0, bh1);
                }
            }
        }
    }
#pragma unroll
    for (int mt = 0; mt < 2; mt++) {
        int m0 = w * 32 + mt * 16 + g;
        float b0 = bb[m0], b8 = bb[m0 + 8];
#pragma unroll
        for (int nt = 0; nt < 8; nt++) {
            size_t r0 = row0 + nt * 8 + 2 * tig;
            float v;
            v = acc[mt][nt][0] + b0; eP[r0 * 256 + m0]           = v > 0.f ? v : 0.f;
            v = acc[mt][nt][1] + b0; eP[(r0 + 1) * 256 + m0]     = v > 0.f ? v : 0.f;
            v = acc[mt][nt][2] + b8; eP[r0 * 256 + m0 + 8]       = v > 0.f ? v : 0.f;
            v = acc[mt][nt][3] + b8; eP[(r0 + 1) * 256 + m0 + 8] = v > 0.f ? v : 0.f;
        }
    }
}

// --------------------------- tail kernel (HMMA) -----------------------------
// 32 rows/CTA (sorted), 256 threads, 2 CTAs/SM. Split-bf16 smem planes,
// stride SR u16 per row. GEMM1 (lerped Wv) -> xs; GEMM2 (branch W5c) -> h1;
// GEMM3 (Wc2) -> out.
#define SR 264
#define T_E0H 0
#define T_E0L 8448
#define T_E1H 16896
#define T_E1L 25344
#define T_XSH 33792
#define T_XSL 42240
#define T_FLT 50688
#define TAIL_SMEM 102400

__device__ __forceinline__ void lpk(const u16* eh0, const u16* el0,
                                    const u16* eh1, const u16* el1,
                                    float a0, u32& bh, u32& bl) {
    u32 xh0 = *(const u32*)eh0, xl0 = *(const u32*)el0;
    u32 xh1 = *(const u32*)eh1, xl1 = *(const u32*)el1;
    float e0a = b2f(xh0 & 0xffffu) + b2f(xl0 & 0xffffu);
    float e0b = b2f(xh0 >> 16) + b2f(xl0 >> 16);
    float e1a = b2f(xh1 & 0xffffu) + b2f(xl1 & 0xffffu);
    float e1b = b2f(xh1 >> 16) + b2f(xl1 >> 16);
    float va = fmaf(a0, e0a - e1a, e1a), vb = fmaf(a0, e0b - e1b, e1b);
    u16 ha, la, hb, lb;
    splitf(va, ha, la); splitf(vb, hb, lb);
    bh = (u32)ha | ((u32)hb << 16);
    bl = (u32)la | ((u32)lb << 16);
}

__global__ void __launch_bounds__(256, 2)
tail_mma(const float* __restrict__ img, const float* __restrict__ txt,
         const float* __restrict__ bc1, const float* __restrict__ bc2,
         float* __restrict__ out) {
    extern __shared__ u16 sh[];
    u16* E0H = sh + T_E0H; u16* E0L = sh + T_E0L;
    u16* E1H = sh + T_E1H; u16* E1L = sh + T_E1L;
    u16* XSH = sh + T_XSH; u16* XSL = sh + T_XSL;
    float* sattn = (float*)(sh + T_FLT);
    int* sflag = (int*)(sattn + 128);
    int* sperm = sflag + 32;
    int* ssbr  = sperm + 32;
    int* snb   = ssbr + 32;
    float* scratch = (float*)(sh + T_XSH);  // overlays xs (dead until GEMM1 epi)

    const int tid = threadIdx.x, lane = tid & 31, w = tid >> 5;
    const int g = lane >> 2, tig = lane & 3;
    const size_t row0 = (size_t)blockIdx.x * 32;

    // P0: flags + sort
    for (int l = 0; l < 2; l++) {
        int task = tid + l * 256;
        int mod = task >> 8, r = (task >> 3) & 31, p = task & 7;
        const float* X = mod ? txt : img;
        const float4* xp = (const float4*)(X + (row0 + r) * 512 + p * 64);
        float s = 0.f;
#pragma unroll
        for (int u = 0; u < 16; u++) {
            float4 v = xp[u];
            s += v.x * v.x + v.y * v.y + v.z * v.z + v.w * v.w;
        }
        scratch[task] = s;
    }
    __syncthreads();
    if (tid < 32) {
        float si = 0.f, st = 0.f;
#pragma unroll
        for (int p = 0; p < 8; p++) { si += scratch[tid * 8 + p]; st += scratch[256 + tid * 8 + p]; }
        int fi = si > 1e-12f, ft = st > 1e-12f;
        sflag[tid] = (fi && ft) ? 1 : (fi ? 2 : (ft ? 3 : 0));
    }
    __syncthreads();
    if (tid == 0) {
        int cnt[4] = {0, 0, 0, 0};
        for (int r = 0; r < 32; r++) cnt[sflag[r]]++;
        int base[4];
        base[1] = 0; base[2] = cnt[1]; base[3] = cnt[1] + cnt[2]; base[0] = base[3] + cnt[3];
        for (int r = 0; r < 32; r++) {
            int f = sflag[r], s = base[f]++;
            sperm[s] = r; ssbr[s] = f;
        }
        *snb = cnt[1];
    }
    __syncthreads();

    // P1: stage e0/e1 split-bf16 (sorted) + per-head dot partials
    {
        int s = tid >> 3, p = tid & 7;
        size_t gr = row0 + sperm[s];
        int k0 = p * 32;
        float d[2][4] = {};
        for (int m2 = 0; m2 < 2; m2++) {
            const float* src = (m2 ? g_e1 : g_e0) + gr * 256 + k0;
            u16* PH = m2 ? E1H : E0H;
            u16* PL = m2 ? E1L : E0L;
#pragma unroll
            for (int q = 0; q < 8; q++) {
                float4 v = *(const float4*)(src + q * 4);
                float vv[4] = {v.x, v.y, v.z, v.w};
#pragma unroll
                for (int e = 0; e < 4; e++) {
                    int k = k0 + q * 4 + e;
                    u16 hh, ll;
                    splitf(vv[e], hh, ll);
                    PH[s * SR + k] = hh; PL[s * SR + k] = ll;
#pragma unroll
                    for (int h = 0; h < 4; h++) d[m2][h] = fmaf(vv[e], g_wk[h * 256 + k], d[m2][h]);
                }
            }
        }
#pragma unroll
        for (int h = 0; h < 4; h++) {
            scratch[(s * 8 + p) * 4 + h] = d[0][h];
            scratch[1024 + (s * 8 + p) * 4 + h] = d[1][h];
        }
    }
    __syncthreads();
    if (tid < 128) {
        int s = tid >> 2, h = tid & 3;
        float d0 = 0.f, d1 = 0.f;
#pragma unroll
        for (int p = 0; p < 8; p++) {
            d0 += scratch[(s * 8 + p) * 4 + h];
            d1 += scratch[1024 + (s * 8 + p) * 4 + h];
        }
        float s0 = (d0 + g_ck[h]) * 0.125f, s1 = (d1 + g_ck[h]) * 0.125f;
        float m = fmaxf(s0, s1);
        float e0 = expf(s0 - m), e1 = expf(s1 - m);
        sattn[s * 4 + h] = e0 / (e0 + e1);
    }
    __syncthreads();
    const int nb = *snb;

    // GEMM1: pooled = lerp(e0,e1,a0_h) @ Wv  (both-row tiles only) -> xs
    {
        int h = w >> 1, cw = w * 32;
        float a1[2][4][4] = {};
        if (nb > 0) {
            for (int ks = 0; ks < 16; ks++) {
                u32 ah[2][4], al[2][4];
#pragma unroll
                for (int mt = 0; mt < 2; mt++) {
                    int m = cw + mt * 16 + g;
                    size_t o = (size_t)m * 256 + ks * 16 + 2 * tig, o8 = o + 2048;
                    ah[mt][0] = *(const u32*)(g_Wvh + o); ah[mt][1] = *(const u32*)(g_Wvh + o8);
                    ah[mt][2] = *(const u32*)(g_Wvh + o + 8); ah[mt][3] = *(const u32*)(g_Wvh + o8 + 8);
                    al[mt][0] = *(const u32*)(g_Wvl + o); al[mt][1] = *(const u32*)(g_Wvl + o8);
                    al[mt][2] = *(const u32*)(g_Wvl + o + 8); al[mt][3] = *(const u32*)(g_Wvl + o8 + 8);
                }
                for (int nt = 0; nt < 4; nt++) {
                    if (nt * 8 >= nb) break;
                    int s = nt * 8 + g;
                    float a0 = sattn[s * 4 + h];
                    int base = s * SR + ks * 16 + 2 * tig;
                    u32 bh0, bl0, bh1, bl1;
                    lpk(E0H + base, E0L + base, E1H + base, E1L + base, a0, bh0, bl0);
                    lpk(E0H + base + 8, E0L + base + 8, E1H + base + 8, E1L + base + 8, a0, bh1, bl1);
#pragma unroll
                    for (int mt = 0; mt < 2; mt++) {
                        MMA16816(a1[mt][nt], ah[mt], bh0, bh1);
                        MMA16816(a1[mt][nt], ah[mt], bl0, bl1);
                        MMA16816(a1[mt][nt], al[mt], bh0, bh1);
                    }
                }
            }
            for (int nt = 0; nt < 4 && nt * 8 < nb; nt++)
#pragma unroll
                for (int mt = 0; mt < 2; mt++) {
                    int r0 = nt * 8 + 2 * tig, m0 = cw + mt * 16 + g;
                    u16 hh, ll;
                    if (r0 < nb) {
                        splitf(a1[mt][nt][0], hh, ll); XSH[r0 * SR + m0] = hh; XSL[r0 * SR + m0] = ll;
                        splitf(a1[mt][nt][2], hh, ll); XSH[r0 * SR + m0 + 8] = hh; XSL[r0 * SR + m0 + 8] = ll;
                    }
                    if (r0 + 1 < nb) {
                        splitf(a1[mt][nt][1], hh, ll); XSH[(r0 + 1) * SR + m0] = hh; XSL[(r0 + 1) * SR + m0] = ll;
                        splitf(a1[mt][nt][3], hh, ll); XSH[(r0 + 1) * SR + m0 + 8] = hh; XSL[(r0 + 1) * SR + m0 + 8] = ll;
                    }
                }
        }
    }
    __syncthreads();

    // P4: xs for non-both rows (copy e0/e1 or zero)
    for (int idx = tid; idx < 32 * 8; idx += 256) {
        int s = idx >> 3, q = idx & 7;
        if (s < nb) continue;
        int f = ssbr[s];
        uint4 z = make_uint4(0, 0, 0, 0);
#pragma unroll
        for (int j = 0; j < 4; j++) {
            uint4 vh = z, vl = z;
            if (f == 2) {
                vh = ((const uint4*)(E0H + s * SR))[q * 4 + j];
                vl = ((const uint4*)(E0L + s * SR))[q * 4 + j];
            } else if (f == 3) {
                vh = ((const uint4*)(E1H + s * SR))[q * 4 + j];
                vl = ((const uint4*)(E1L + s * SR))[q * 4 + j];
            }
            ((uint4*)(XSH + s * SR))[q * 4 + j] = vh;
            ((uint4*)(XSL + s * SR))[q * 4 + j] = vl;
        }
    }
    __syncthreads();

    // GEMM2: h1 = relu(xs @ W5c[branch] + bias) -> overlay e0 planes
    {
        int cw = w * 32;
        float a2[2][4][4] = {};
        for (int seg = 1; seg <= 3; seg++) {
            u32 ntm = 0;
            for (int i = 0; i < 32; i++)
                if (ssbr[i] == seg) ntm |= 1u << (i >> 3);
            if (!ntm) continue;
            const u16* WH = g_W5h + (size_t)(seg - 1) * 65536;
            const u16* WL = g_W5l + (size_t)(seg - 1) * 65536;
            for (int ks = 0; ks < 16; ks++) {
                u32 ah[2][4], al[2][4];
#pragma unroll
                for (int mt = 0; mt < 2; mt++) {
                    int m = cw + mt * 16 + g;
                    size_t o = (size_t)m * 256 + ks * 16 + 2 * tig, o8 = o + 2048;
                    ah[mt][0] = *(const u32*)(WH + o); ah[mt][1] = *(const u32*)(WH + o8);
                    ah[mt][2] = *(const u32*)(WH + o + 8); ah[mt][3] = *(const u32*)(WH + o8 + 8);
                    al[mt][0] = *(const u32*)(WL + o); al[mt][1] = *(const u32*)(WL + o8);
                    al[mt][2] = *(const u32*)(WL + o + 8); al[mt][3] = *(const u32*)(WL + o8 + 8);
                }
                for (int nt = 0; nt < 4; nt++) {
                    if (!((ntm >> nt) & 1)) continue;
                    int s = nt * 8 + g;
                    bool on = (ssbr[s] == seg);
                    int base = s * SR + ks * 16 + 2 * tig;
                    u32 bh0 = 0, bh1 = 0, bl0 = 0, bl1 = 0;
                    if (on) {
                        bh0 = *(const u32*)(XSH + base); bh1 = *(const u32*)(XSH + base + 8);
                        bl0 = *(const u32*)(XSL + base); bl1 = *(const u32*)(XSL + base + 8);
                    }
#pragma unroll
                    for (int mt = 0; mt < 2; mt++) {
                        MMA16816(a2[mt][nt], ah[mt], bh0, bh1);
                        MMA16816(a2[mt][nt], ah[mt], bl0, bl1);
                        MMA16816(a2[mt][nt], al[mt], bh0, bh1);
                    }
                }
            }
        }
        for (int nt = 0; nt < 4; nt++)
#pragma unroll
            for (int mt = 0; mt < 2; mt++) {
                int r0 = nt * 8 + 2 * tig, m0 = cw + mt * 16 + g;
#pragma unroll
                for (int pr = 0; pr < 2; pr++) {
                    int r = r0 + pr;
                    int f = ssbr[r];
                    float b0 = f ? g_b5c[(f - 1) * 256 + m0] : bc1[m0];
                    float b8 = f ? g_b5c[(f - 1) * 256 + m0 + 8] : bc1[m0 + 8];
                    float v0 = a2[mt][nt][pr] + b0;     v0 = v0 > 0.f ? v0 : 0.f;
                    float v8 = a2[mt][nt][2 + pr] + b8; v8 = v8 > 0.f ? v8 : 0.f;
                    u16 hh, ll;
                    splitf(v0, hh, ll); E0H[r * SR + m0] = hh;     E0L[r * SR + m0] = ll;
                    splitf(v8, hh, ll); E0H[r * SR + m0 + 8] = hh; E0L[r * SR + m0 + 8] = ll;
                }
            }
    }
    __syncthreads();

    // GEMM3: out = h1 @ Wc2 + bc2 (warps 0..4, 16 cols each)
    if (w < 5) {
        float a3[4][4] = {};
        for (int ks = 0; ks < 16; ks++) {
            int m = w * 16 + g;
            size_t o = (size_t)m * 256 + ks * 16 + 2 * tig, o8 = o + 2048;
            u32 ah[4] = {*(const u32*)(g_Wch + o), *(const u32*)(g_Wch + o8),
                         *(const u32*)(g_Wch + o + 8), *(const u32*)(g_Wch + o8 + 8)};
            u32 al[4] = {*(const u32*)(g_Wcl + o), *(const u32*)(g_Wcl + o8),
                         *(const u32*)(g_Wcl + o + 8), *(const u32*)(g_Wcl + o8 + 8)};
#pragma unroll
            for (int nt = 0; nt < 4; nt++) {
                int base = (nt * 8 + g) * SR + ks * 16 + 2 * tig;
                u32 bh0 = *(const u32*)(E0H + base), bh1 = *(const u32*)(E0H + base + 8);
                u32 bl0 = *(const u32*)(E0L + base), bl1 = *(const u32*)(E0L + base + 8);
                MMA16816(a3[nt], ah, bh0, bh1);
                MMA16816(a3[nt], ah, bl0, bl1);
                MMA16816(a3[nt], al, bh0, bh1);
            }
        }
#pragma unroll
        for (int nt = 0; nt < 4; nt++) {
            int r0 = nt * 8 + 2 * tig, m0 = w * 16 + g;
#pragma unroll
            for (int pr = 0; pr < 2; pr++) {
                size_t ro = (row0 + sperm[r0 + pr]) * 80;
                out[ro + m0]     = a3[nt][pr] + bc2[m0];
                out[ro + m0 + 8] = a3[nt][2 + pr] + bc2[m0 + 8];
            }
        }
    }
}

// ------------------------------- launch ------------------------------------
extern "C" void kernel_launch(void* const* d_in, const int* in_sizes, int n_in,
                              void* d_out, int out_size) {
    const float* img  = (const float*)d_in[0];
    const float* txt  = (const float*)d_in[1];
    const float* W_ie = (const float*)d_in[2];
    const float* b_ie = (const float*)d_in[3];
    const float* W_te = (const float*)d_in[4];
    const float* b_te = (const float*)d_in[5];
    const float* fq   = (const float*)d_in[6];
    const float* Wq   = (const float*)d_in[7];
    const float* bq   = (const float*)d_in[8];
    const float* Wk   = (const float*)d_in[9];
    const float* bk   = (const float*)d_in[10];
    const float* Wv   = (const float*)d_in[11];
    const float* bv   = (const float*)d_in[12];
    const float* Wo   = (const float*)d_in[13];
    const float* bo   = (const float*)d_in[14];
    const float* W_ip = (const float*)d_in[15];
    const float* b_ip = (const float*)d_in[16];
    const float* W_tp = (const float*)d_in[17];
    const float* b_tp = (const float*)d_in[18];
    const float* W_fp = (const float*)d_in[19];
    const float* b_fp = (const float*)d_in[20];
    const float* Wc1  = (const float*)d_in[21];
    const float* bc1  = (const float*)d_in[22];
    const float* Wc2  = (const float*)d_in[23];
    const float* bc2  = (const float*)d_in[24];
    float* out = (float*)d_out;

    const int B = in_sizes[0] / 512;

    setup_all<<<17, 256>>>(fq, Wq, bq, Wk, bk, bv, Wo, bo, W_fp, b_fp);
    setup_fuse<<<25, 256>>>(W_ip, W_tp, Wc1, b_ip, b_tp, bc1);
    setup_conv<<<1024, 256>>>(W_ie, W_te);
    setup_conv2<<<1104, 256>>>(Wv, Wc2);

    cudaFuncSetAttribute(enc_kernel, cudaFuncAttributeMaxDynamicSharedMemorySize,
                         ENC_SMEM);
    enc_kernel<<<dim3(B / 64, 2), 256, ENC_SMEM>>>(img, txt, b_ie, b_te);

    cudaFuncSetAttribute(tail_mma, cudaFuncAttributeMaxDynamicSharedMemorySize,
                         TAIL_SMEM);
    tail_mma<<<B / 32, 256, TAIL_SMEM>>>(img, txt, bc1, bc2, out);
}